// round 3
// baseline (speedup 1.0000x reference)
#include <cuda_runtime.h>

#define D 64
#define NMAX 100000
#define EMAX 1600000

typedef unsigned long long u64;

// ---------------- scratch (static device globals) ----------------
__device__ float g_h[NMAX * D];    // h (GCN) then h2 (GAT)
__device__ float g_x[NMAX * D];    // GCN output x, then diffused
__device__ float g_as[NMAX];
__device__ float g_ad[NMAX];
__device__ float g_dinv[NMAX];
__device__ int   g_cnt[NMAX];
__device__ int   g_rs[NMAX];
__device__ int   g_cur[NMAX];
__device__ int   g_bsum[256];
__device__ int   g_csrc[EMAX];

// ---------------- packed f32x2 helpers ----------------
__device__ __forceinline__ void fma2(u64& acc, u64 a, u64 b) {
    asm("fma.rn.f32x2 %0, %1, %2, %0;" : "+l"(acc) : "l"(a), "l"(b));
}
__device__ __forceinline__ u64 pack2(float lo, float hi) {
    u64 d; asm("mov.b64 %0, {%1, %2};" : "=l"(d) : "f"(lo), "f"(hi)); return d;
}
__device__ __forceinline__ float2 unpack2(u64 v) {
    float2 r; asm("mov.b64 {%0, %1}, %2;" : "=f"(r.x), "=f"(r.y) : "l"(v)); return r;
}
__device__ __forceinline__ float sigmoidf_(float x) { return 1.0f / (1.0f + __expf(-x)); }

// ---------------- CSR build ----------------
__global__ void k_zero(int n) {
    int i = blockIdx.x * blockDim.x + threadIdx.x;
    if (i < n) g_cnt[i] = 0;
}
__global__ void k_cnt(const int* __restrict__ ei, int E) {
    int e = blockIdx.x * blockDim.x + threadIdx.x;
    if (e < E) atomicAdd(&g_cnt[ei[E + e]], 1);
}
__global__ void k_scanA(int n) {
    __shared__ int s[1024];
    int tid = threadIdx.x;
    int i = blockIdx.x * 1024 + tid;
    int v = (i < n) ? g_cnt[i] : 0;
    s[tid] = v; __syncthreads();
    for (int off = 1; off < 1024; off <<= 1) {
        int t = (tid >= off) ? s[tid - off] : 0;
        __syncthreads();
        s[tid] += t; __syncthreads();
    }
    if (i < n) g_rs[i] = s[tid] - v;
    if (tid == 1023) g_bsum[blockIdx.x] = s[1023];
}
__global__ void k_scanB(int nb) {
    __shared__ int s[128];
    int tid = threadIdx.x;
    int v = (tid < nb) ? g_bsum[tid] : 0;
    s[tid] = v; __syncthreads();
    for (int off = 1; off < 128; off <<= 1) {
        int t = (tid >= off) ? s[tid - off] : 0;
        __syncthreads();
        s[tid] += t; __syncthreads();
    }
    if (tid < nb) g_bsum[tid] = s[tid] - v;
}
__global__ void k_scanC(int n) {
    int i = blockIdx.x * blockDim.x + threadIdx.x;
    if (i >= n) return;
    int base = g_bsum[i >> 10];
    int r = g_rs[i] + base;
    g_rs[i] = r;
    g_cur[i] = r;
    g_dinv[i] = rsqrtf((float)g_cnt[i] + 1.0f);
}
__global__ void k_csr(const int* __restrict__ ei, int E) {
    int e = blockIdx.x * blockDim.x + threadIdx.x;
    if (e >= E) return;
    int s = ei[e], d = ei[E + e];
    int p = atomicAdd(&g_cur[d], 1);
    g_csrc[p] = s;
}

// ---------------- fused encoder + GCN weight GEMM (f32x2, 64-row tile) ----------------
// dyn smem (u64 units): evd[8*65] | t1d[64*65] | t2d[64*65] | then Wb float4[1024]
__global__ void k_encgemm(const float* __restrict__ ev,
                          const float* __restrict__ W1, const float* __restrict__ b1,
                          const float* __restrict__ W2, const float* __restrict__ b2,
                          const float* __restrict__ gcnW, int n) {
    extern __shared__ u64 smu[];
    u64* evd = smu;              // 520
    u64* t1d = smu + 520;        // 4160
    u64* t2d = smu + 4680;       // 4160
    float4* Wb = (float4*)(smu + 8840);  // 1024 float4

    int tid = threadIdx.x;
    int c4 = tid & 15, rq = tid >> 4;
    int row0 = blockIdx.x * 64;

    // load ev duplicated: evd[k][r]
    for (int i = tid; i < 512; i += 256) {
        int rr = i >> 3, cc = i & 7;
        int gr = row0 + rr;
        float v = (gr < n) ? ev[gr * 8 + cc] : 0.0f;
        evd[cc * 65 + rr] = pack2(v, v);
    }
    if (tid < 128) Wb[tid] = ((const float4*)W1)[tid];
    __syncthreads();

    u64 alo[4], ahi[4];
    {
        u64 bl = pack2(b1[c4 * 4], b1[c4 * 4 + 1]);
        u64 bh = pack2(b1[c4 * 4 + 2], b1[c4 * 4 + 3]);
#pragma unroll
        for (int m = 0; m < 4; m++) { alo[m] = bl; ahi[m] = bh; }
    }
#pragma unroll
    for (int k = 0; k < 8; k++) {
        ulonglong2 w = ((const ulonglong2*)Wb)[k * 16 + c4];
#pragma unroll
        for (int m = 0; m < 4; m++) {
            u64 x = evd[k * 65 + rq + 16 * m];
            fma2(alo[m], x, w.x); fma2(ahi[m], x, w.y);
        }
    }
#pragma unroll
    for (int m = 0; m < 4; m++) {
        int rm = rq + 16 * m;
        float2 p0 = unpack2(alo[m]), p1 = unpack2(ahi[m]);
        float v0 = fmaxf(p0.x, 0.f), v1 = fmaxf(p0.y, 0.f);
        float v2 = fmaxf(p1.x, 0.f), v3 = fmaxf(p1.y, 0.f);
        t1d[(c4 * 4 + 0) * 65 + rm] = pack2(v0, v0);
        t1d[(c4 * 4 + 1) * 65 + rm] = pack2(v1, v1);
        t1d[(c4 * 4 + 2) * 65 + rm] = pack2(v2, v2);
        t1d[(c4 * 4 + 3) * 65 + rm] = pack2(v3, v3);
    }
    __syncthreads();
    for (int i = tid; i < 1024; i += 256) Wb[i] = ((const float4*)W2)[i];
    __syncthreads();

    {
        u64 bl = pack2(b2[c4 * 4], b2[c4 * 4 + 1]);
        u64 bh = pack2(b2[c4 * 4 + 2], b2[c4 * 4 + 3]);
#pragma unroll
        for (int m = 0; m < 4; m++) { alo[m] = bl; ahi[m] = bh; }
    }
#pragma unroll 8
    for (int k = 0; k < 64; k++) {
        ulonglong2 w = ((const ulonglong2*)Wb)[k * 16 + c4];
#pragma unroll
        for (int m = 0; m < 4; m++) {
            u64 x = t1d[k * 65 + rq + 16 * m];
            fma2(alo[m], x, w.x); fma2(ahi[m], x, w.y);
        }
    }
#pragma unroll
    for (int m = 0; m < 4; m++) {
        int rm = rq + 16 * m;
        float2 p0 = unpack2(alo[m]), p1 = unpack2(ahi[m]);
        t2d[(c4 * 4 + 0) * 65 + rm] = pack2(p0.x, p0.x);
        t2d[(c4 * 4 + 1) * 65 + rm] = pack2(p0.y, p0.y);
        t2d[(c4 * 4 + 2) * 65 + rm] = pack2(p1.x, p1.x);
        t2d[(c4 * 4 + 3) * 65 + rm] = pack2(p1.y, p1.y);
    }
    __syncthreads();
    for (int i = tid; i < 1024; i += 256) Wb[i] = ((const float4*)gcnW)[i];
    __syncthreads();

#pragma unroll
    for (int m = 0; m < 4; m++) { alo[m] = 0ull; ahi[m] = 0ull; }
#pragma unroll 8
    for (int k = 0; k < 64; k++) {
        ulonglong2 w = ((const ulonglong2*)Wb)[k * 16 + c4];
#pragma unroll
        for (int m = 0; m < 4; m++) {
            u64 x = t2d[k * 65 + rq + 16 * m];
            fma2(alo[m], x, w.x); fma2(ahi[m], x, w.y);
        }
    }
#pragma unroll
    for (int m = 0; m < 4; m++) {
        int row = row0 + rq + 16 * m;
        if (row < n) {
            float2 p0 = unpack2(alo[m]), p1 = unpack2(ahi[m]);
            ((float4*)g_h)[row * 16 + c4] = make_float4(p0.x, p0.y, p1.x, p1.y);
        }
    }
}

// ---------------- g_x @ W -> g_h (f32x2, 64-row tile) ----------------
__global__ void k_gemm64v3(const float* __restrict__ W, int n) {
    extern __shared__ u64 smu[];
    u64* xd = smu;                        // 4160
    float4* Wb = (float4*)(smu + 4160);   // 1024 float4

    int tid = threadIdx.x;
    int c4 = tid & 15, rq = tid >> 4;
    int row0 = blockIdx.x * 64;

    for (int i = tid; i < 1024; i += 256) {
        int rr = i >> 4, cc = i & 15;
        int gr = row0 + rr;
        float4 v = make_float4(0.f, 0.f, 0.f, 0.f);
        if (gr < n) v = ((const float4*)g_x)[gr * 16 + cc];
        xd[(cc * 4 + 0) * 65 + rr] = pack2(v.x, v.x);
        xd[(cc * 4 + 1) * 65 + rr] = pack2(v.y, v.y);
        xd[(cc * 4 + 2) * 65 + rr] = pack2(v.z, v.z);
        xd[(cc * 4 + 3) * 65 + rr] = pack2(v.w, v.w);
    }
    for (int i = tid; i < 1024; i += 256) Wb[i] = ((const float4*)W)[i];
    __syncthreads();

    u64 alo[4] = {0, 0, 0, 0}, ahi[4] = {0, 0, 0, 0};
#pragma unroll 8
    for (int k = 0; k < 64; k++) {
        ulonglong2 w = ((const ulonglong2*)Wb)[k * 16 + c4];
#pragma unroll
        for (int m = 0; m < 4; m++) {
            u64 x = xd[k * 65 + rq + 16 * m];
            fma2(alo[m], x, w.x); fma2(ahi[m], x, w.y);
        }
    }
#pragma unroll
    for (int m = 0; m < 4; m++) {
        int row = row0 + rq + 16 * m;
        if (row < n) {
            float2 p0 = unpack2(alo[m]), p1 = unpack2(ahi[m]);
            ((float4*)g_h)[row * 16 + c4] = make_float4(p0.x, p0.y, p1.x, p1.y);
        }
    }
}

// ---------------- GCN pull aggregation (warp/node, MLP-4 inner) ----------------
__global__ void k_gcn_agg(const float* __restrict__ b, int n) {
    int gt = blockIdx.x * blockDim.x + threadIdx.x;
    int d = gt >> 5, lane = gt & 31;
    if (d >= n) return;
    const float2* H2 = (const float2*)g_h;
    float dinv_d = g_dinv[d];
    float2 hv = H2[d * 32 + lane];
    float sn = dinv_d * dinv_d;
    float ax = hv.x * sn, ay = hv.y * sn;
    int beg = g_rs[d], cnt = g_cnt[d];
    for (int c0 = 0; c0 < cnt; c0 += 32) {
        int idx = c0 + lane;
        int s = 0; float nm = 0.f;
        if (idx < cnt) { s = __ldg(&g_csrc[beg + idx]); nm = g_dinv[s] * dinv_d; }
        int m = min(32, cnt - c0);
        int j = 0;
        for (; j + 4 <= m; j += 4) {
            int s0 = __shfl_sync(0xffffffffu, s, j);
            int s1 = __shfl_sync(0xffffffffu, s, j + 1);
            int s2 = __shfl_sync(0xffffffffu, s, j + 2);
            int s3 = __shfl_sync(0xffffffffu, s, j + 3);
            float n0 = __shfl_sync(0xffffffffu, nm, j);
            float n1 = __shfl_sync(0xffffffffu, nm, j + 1);
            float n2 = __shfl_sync(0xffffffffu, nm, j + 2);
            float n3 = __shfl_sync(0xffffffffu, nm, j + 3);
            float2 v0 = H2[s0 * 32 + lane];
            float2 v1 = H2[s1 * 32 + lane];
            float2 v2 = H2[s2 * 32 + lane];
            float2 v3 = H2[s3 * 32 + lane];
            ax = fmaf(n0, v0.x, ax); ay = fmaf(n0, v0.y, ay);
            ax = fmaf(n1, v1.x, ax); ay = fmaf(n1, v1.y, ay);
            ax = fmaf(n2, v2.x, ax); ay = fmaf(n2, v2.y, ay);
            ax = fmaf(n3, v3.x, ax); ay = fmaf(n3, v3.y, ay);
        }
        for (; j < m; j++) {
            int sj = __shfl_sync(0xffffffffu, s, j);
            float nj = __shfl_sync(0xffffffffu, nm, j);
            float2 v = H2[sj * 32 + lane];
            ax = fmaf(nj, v.x, ax); ay = fmaf(nj, v.y, ay);
        }
    }
    float2 bb = ((const float2*)b)[lane];
    float2 o;
    o.x = fmaxf(ax + bb.x, 0.f);
    o.y = fmaxf(ay + bb.y, 0.f);
    ((float2*)g_x)[d * 32 + lane] = o;
}

// ---------------- GAT per-node attention coefficients ----------------
__global__ void k_gat_node(const float* __restrict__ att_s, const float* __restrict__ att_d, int n) {
    int gt = blockIdx.x * blockDim.x + threadIdx.x;
    int node = gt >> 5, lane = gt & 31;
    if (node >= n) return;
    float h0 = g_h[node * 64 + lane];
    float h1 = g_h[node * 64 + 32 + lane];
    float as = h0 * att_s[lane] + h1 * att_s[32 + lane];
    float ad = h0 * att_d[lane] + h1 * att_d[32 + lane];
#pragma unroll
    for (int o = 16; o; o >>= 1) {
        as += __shfl_xor_sync(0xffffffffu, as, o);
        ad += __shfl_xor_sync(0xffffffffu, ad, o);
    }
    if (lane == 0) { g_as[node] = as; g_ad[node] = ad; }
}

// ---------------- GAT pull aggregation (warp/node, MLP-4 inner) ----------------
__global__ void k_gat_agg(const float* __restrict__ b, int n) {
    int gt = blockIdx.x * blockDim.x + threadIdx.x;
    int d = gt >> 5, lane = gt & 31;
    if (d >= n) return;
    const float2* H2 = (const float2*)g_h;
    float ad_d = g_ad[d];
    float e0 = g_as[d] + ad_d;
    float l0 = e0 > 0.f ? e0 : 0.2f * e0;
    float wself = __expf(l0);
    float2 hd = H2[d * 32 + lane];
    float ax = wself * hd.x, ay = wself * hd.y;
    float zp = (lane == 0) ? wself : 0.f;
    int beg = g_rs[d], cnt = g_cnt[d];
    for (int c0 = 0; c0 < cnt; c0 += 32) {
        int idx = c0 + lane;
        int s = 0; float w = 0.f;
        if (idx < cnt) {
            s = __ldg(&g_csrc[beg + idx]);
            float ev = g_as[s] + ad_d;
            float lr = ev > 0.f ? ev : 0.2f * ev;
            w = __expf(lr);
        }
        zp += w;
        int m = min(32, cnt - c0);
        int j = 0;
        for (; j + 4 <= m; j += 4) {
            int s0 = __shfl_sync(0xffffffffu, s, j);
            int s1 = __shfl_sync(0xffffffffu, s, j + 1);
            int s2 = __shfl_sync(0xffffffffu, s, j + 2);
            int s3 = __shfl_sync(0xffffffffu, s, j + 3);
            float w0 = __shfl_sync(0xffffffffu, w, j);
            float w1 = __shfl_sync(0xffffffffu, w, j + 1);
            float w2 = __shfl_sync(0xffffffffu, w, j + 2);
            float w3 = __shfl_sync(0xffffffffu, w, j + 3);
            float2 v0 = H2[s0 * 32 + lane];
            float2 v1 = H2[s1 * 32 + lane];
            float2 v2 = H2[s2 * 32 + lane];
            float2 v3 = H2[s3 * 32 + lane];
            ax = fmaf(w0, v0.x, ax); ay = fmaf(w0, v0.y, ay);
            ax = fmaf(w1, v1.x, ax); ay = fmaf(w1, v1.y, ay);
            ax = fmaf(w2, v2.x, ax); ay = fmaf(w2, v2.y, ay);
            ax = fmaf(w3, v3.x, ax); ay = fmaf(w3, v3.y, ay);
        }
        for (; j < m; j++) {
            int sj = __shfl_sync(0xffffffffu, s, j);
            float wj = __shfl_sync(0xffffffffu, w, j);
            float2 v = H2[sj * 32 + lane];
            ax = fmaf(wj, v.x, ax); ay = fmaf(wj, v.y, ay);
        }
    }
#pragma unroll
    for (int o = 16; o; o >>= 1) zp += __shfl_xor_sync(0xffffffffu, zp, o);
    float inv = 1.0f / zp;
    float2 bb = ((const float2*)b)[lane];
    float2 o2;
    o2.x = fmaxf(fmaf(ax, inv, bb.x), 0.f);
    o2.y = fmaxf(fmaf(ay, inv, bb.y), 0.f);
    ((float2*)g_x)[d * 32 + lane] = o2;
}

// ---------------- fused gate + residual + speed head (f32x2, 64-row, 512 thr) --------
// dyn smem (u64 units): fusd[128*65]=8320 | t1d[64*65]=4160 | Wb f4[2048] | tb f[64*34]
__global__ void k_final(const float* __restrict__ H,
                        const float* __restrict__ gate_W, const float* __restrict__ gate_b,
                        const float* __restrict__ res_W1, const float* __restrict__ res_b1,
                        const float* __restrict__ res_W2, const float* __restrict__ res_b2,
                        const float* __restrict__ sp_W1, const float* __restrict__ sp_b1,
                        const float* __restrict__ sp_W2, const float* __restrict__ sp_b2,
                        float* __restrict__ delta_out, float* __restrict__ hf_out,
                        float* __restrict__ pred_out, int n) {
    extern __shared__ u64 smu[];
    u64* fusd = smu;                        // 8320
    u64* t1d  = smu + 8320;                 // 4160
    float4* Wb = (float4*)(smu + 12480);    // 2048 float4 = 32KB
    float* tb  = (float*)(Wb + 2048);       // 64*34 floats

    int tid = threadIdx.x;
    int c4 = tid & 15, rq = tid >> 4;       // rq 0..31, rows rq, rq+32
    int row0 = blockIdx.x * 64;

    // load fusion = [H | diffused] duplicated: fusd[k][r], k 0..127
    for (int i = tid; i < 2048; i += 512) {
        int rr = i >> 5, j = i & 31;
        int gr = row0 + rr;
        float4 v = make_float4(0.f, 0.f, 0.f, 0.f);
        if (gr < n) v = (j < 16) ? ((const float4*)H)[gr * 16 + j]
                                 : ((const float4*)g_x)[gr * 16 + (j - 16)];
        fusd[(j * 4 + 0) * 65 + rr] = pack2(v.x, v.x);
        fusd[(j * 4 + 1) * 65 + rr] = pack2(v.y, v.y);
        fusd[(j * 4 + 2) * 65 + rr] = pack2(v.z, v.z);
        fusd[(j * 4 + 3) * 65 + rr] = pack2(v.w, v.w);
    }
    for (int i = tid; i < 2048; i += 512) Wb[i] = ((const float4*)gate_W)[i];
    __syncthreads();

    // ---- gate ----
    u64 alo[2], ahi[2];
    {
        u64 bl = pack2(gate_b[c4 * 4], gate_b[c4 * 4 + 1]);
        u64 bh = pack2(gate_b[c4 * 4 + 2], gate_b[c4 * 4 + 3]);
        alo[0] = alo[1] = bl; ahi[0] = ahi[1] = bh;
    }
#pragma unroll 8
    for (int k = 0; k < 128; k++) {
        ulonglong2 w = ((const ulonglong2*)Wb)[k * 16 + c4];
#pragma unroll
        for (int m = 0; m < 2; m++) {
            u64 x = fusd[k * 65 + rq + 32 * m];
            fma2(alo[m], x, w.x); fma2(ahi[m], x, w.y);
        }
    }
    float gv[2][4];
#pragma unroll
    for (int m = 0; m < 2; m++) {
        float2 p0 = unpack2(alo[m]), p1 = unpack2(ahi[m]);
        gv[m][0] = sigmoidf_(p0.x); gv[m][1] = sigmoidf_(p0.y);
        gv[m][2] = sigmoidf_(p1.x); gv[m][3] = sigmoidf_(p1.y);
    }
    __syncthreads();
    for (int i = tid; i < 2048; i += 512) Wb[i] = ((const float4*)res_W1)[i];
    __syncthreads();

    // ---- res layer 1 ----
    {
        u64 bl = pack2(res_b1[c4 * 4], res_b1[c4 * 4 + 1]);
        u64 bh = pack2(res_b1[c4 * 4 + 2], res_b1[c4 * 4 + 3]);
        alo[0] = alo[1] = bl; ahi[0] = ahi[1] = bh;
    }
#pragma unroll 8
    for (int k = 0; k < 128; k++) {
        ulonglong2 w = ((const ulonglong2*)Wb)[k * 16 + c4];
#pragma unroll
        for (int m = 0; m < 2; m++) {
            u64 x = fusd[k * 65 + rq + 32 * m];
            fma2(alo[m], x, w.x); fma2(ahi[m], x, w.y);
        }
    }
#pragma unroll
    for (int m = 0; m < 2; m++) {
        int rm = rq + 32 * m;
        float2 p0 = unpack2(alo[m]), p1 = unpack2(ahi[m]);
        float v0 = fmaxf(p0.x, 0.f), v1 = fmaxf(p0.y, 0.f);
        float v2 = fmaxf(p1.x, 0.f), v3 = fmaxf(p1.y, 0.f);
        t1d[(c4 * 4 + 0) * 65 + rm] = pack2(v0, v0);
        t1d[(c4 * 4 + 1) * 65 + rm] = pack2(v1, v1);
        t1d[(c4 * 4 + 2) * 65 + rm] = pack2(v2, v2);
        t1d[(c4 * 4 + 3) * 65 + rm] = pack2(v3, v3);
    }
    __syncthreads();
    for (int i = tid; i < 1024; i += 512) Wb[i] = ((const float4*)res_W2)[i];
    __syncthreads();

    // ---- res layer 2 + delta + H_final ----
    {
        u64 bl = pack2(res_b2[c4 * 4], res_b2[c4 * 4 + 1]);
        u64 bh = pack2(res_b2[c4 * 4 + 2], res_b2[c4 * 4 + 3]);
        alo[0] = alo[1] = bl; ahi[0] = ahi[1] = bh;
    }
#pragma unroll 8
    for (int k = 0; k < 64; k++) {
        ulonglong2 w = ((const ulonglong2*)Wb)[k * 16 + c4];
#pragma unroll
        for (int m = 0; m < 2; m++) {
            u64 x = t1d[k * 65 + rq + 32 * m];
            fma2(alo[m], x, w.x); fma2(ahi[m], x, w.y);
        }
    }
    float hfv[2][4];
#pragma unroll
    for (int m = 0; m < 2; m++) {
        int rm = rq + 32 * m;
        int row = row0 + rm;
        float2 p0 = unpack2(alo[m]), p1 = unpack2(ahi[m]);
        float h0 = unpack2(fusd[(c4 * 4 + 0) * 65 + rm]).x;
        float h1 = unpack2(fusd[(c4 * 4 + 1) * 65 + rm]).x;
        float h2 = unpack2(fusd[(c4 * 4 + 2) * 65 + rm]).x;
        float h3 = unpack2(fusd[(c4 * 4 + 3) * 65 + rm]).x;
        float d0 = gv[m][0] * p0.x, d1 = gv[m][1] * p0.y;
        float d2 = gv[m][2] * p1.x, d3 = gv[m][3] * p1.y;
        hfv[m][0] = h0 + d0; hfv[m][1] = h1 + d1;
        hfv[m][2] = h2 + d2; hfv[m][3] = h3 + d3;
        if (row < n) {
            ((float4*)delta_out)[row * 16 + c4] = make_float4(d0, d1, d2, d3);
            ((float4*)hf_out)[row * 16 + c4] = make_float4(hfv[m][0], hfv[m][1], hfv[m][2], hfv[m][3]);
        }
    }
    __syncthreads();  // t1d fully consumed; Wb fully consumed

    // store H_final duplicated into t1d; load sp_W1
#pragma unroll
    for (int m = 0; m < 2; m++) {
        int rm = rq + 32 * m;
        t1d[(c4 * 4 + 0) * 65 + rm] = pack2(hfv[m][0], hfv[m][0]);
        t1d[(c4 * 4 + 1) * 65 + rm] = pack2(hfv[m][1], hfv[m][1]);
        t1d[(c4 * 4 + 2) * 65 + rm] = pack2(hfv[m][2], hfv[m][2]);
        t1d[(c4 * 4 + 3) * 65 + rm] = pack2(hfv[m][3], hfv[m][3]);
    }
    for (int i = tid; i < 512; i += 512) Wb[i] = ((const float4*)sp_W1)[i];
    __syncthreads();

    // ---- speed head layer 1: 2 cols per thread (cols 2*c4, 2*c4+1) ----
    {
        u64 acc[2];
        u64 bpair = pack2(sp_b1[c4 * 2], sp_b1[c4 * 2 + 1]);
        acc[0] = acc[1] = bpair;
#pragma unroll 8
        for (int k = 0; k < 64; k++) {
            u64 w = ((const u64*)Wb)[k * 16 + c4];
#pragma unroll
            for (int m = 0; m < 2; m++) {
                u64 x = t1d[k * 65 + rq + 32 * m];
                fma2(acc[m], x, w);
            }
        }
#pragma unroll
        for (int m = 0; m < 2; m++) {
            int rm = rq + 32 * m;
            float2 p = unpack2(acc[m]);
            tb[rm * 34 + c4 * 2] = fmaxf(p.x, 0.f);
            tb[rm * 34 + c4 * 2 + 1] = fmaxf(p.y, 0.f);
        }
    }
    __syncthreads();
    if (tid < 64) {
        int gr = row0 + tid;
        if (gr < n) {
            float acc = sp_b2[0];
#pragma unroll
            for (int k = 0; k < 32; k++) acc = fmaf(tb[tid * 34 + k], sp_W2[k], acc);
            pred_out[gr] = acc;
        }
    }
}

// ---------------- launch ----------------
extern "C" void kernel_launch(void* const* d_in, const int* in_sizes, int n_in,
                              void* d_out, int out_size) {
    const float* H      = (const float*)d_in[0];
    const float* ev     = (const float*)d_in[1];
    const int*   ei     = (const int*)d_in[2];
    const float* enc_W1 = (const float*)d_in[3];
    const float* enc_b1 = (const float*)d_in[4];
    const float* enc_W2 = (const float*)d_in[5];
    const float* enc_b2 = (const float*)d_in[6];
    const float* gcn_W  = (const float*)d_in[7];
    const float* gcn_b  = (const float*)d_in[8];
    const float* gat_W  = (const float*)d_in[9];
    const float* att_s  = (const float*)d_in[10];
    const float* att_d  = (const float*)d_in[11];
    const float* gat_b  = (const float*)d_in[12];
    const float* gate_W = (const float*)d_in[13];
    const float* gate_b = (const float*)d_in[14];
    const float* res_W1 = (const float*)d_in[15];
    const float* res_b1 = (const float*)d_in[16];
    const float* res_W2 = (const float*)d_in[17];
    const float* res_b2 = (const float*)d_in[18];
    const float* sp_W1  = (const float*)d_in[19];
    const float* sp_b1  = (const float*)d_in[20];
    const float* sp_W2  = (const float*)d_in[21];
    const float* sp_b2  = (const float*)d_in[22];

    int n = in_sizes[0] / 64;
    int E = in_sizes[2] / 2;

    float* delta = (float*)d_out;
    float* hf    = delta + (size_t)n * 64;
    float* pred  = hf + (size_t)n * 64;

    int nb64   = (n + 63) / 64;
    int nbN    = (n + 255) / 256;
    int nbE    = (E + 255) / 256;
    int nb1024 = (n + 1023) / 1024;
    int nbW    = (n * 32 + 255) / 256;

    const int ENC_SMEM = 8840 * 8 + 1024 * 16;                 // 87104
    const int G64_SMEM = 4160 * 8 + 1024 * 16;                 // 49664
    const int FIN_SMEM = 12480 * 8 + 2048 * 16 + 64 * 34 * 4;  // 141312
    cudaFuncSetAttribute(k_encgemm, cudaFuncAttributeMaxDynamicSharedMemorySize, ENC_SMEM);
    cudaFuncSetAttribute(k_gemm64v3, cudaFuncAttributeMaxDynamicSharedMemorySize, G64_SMEM);
    cudaFuncSetAttribute(k_final, cudaFuncAttributeMaxDynamicSharedMemorySize, FIN_SMEM);

    k_zero<<<nbN, 256>>>(n);
    k_cnt<<<nbE, 256>>>(ei, E);
    k_scanA<<<nb1024, 1024>>>(n);
    k_scanB<<<1, 128>>>(nb1024);
    k_scanC<<<nbN, 256>>>(n);
    k_csr<<<nbE, 256>>>(ei, E);
    k_encgemm<<<nb64, 256, ENC_SMEM>>>(ev, enc_W1, enc_b1, enc_W2, enc_b2, gcn_W, n);
    k_gcn_agg<<<nbW, 256>>>(gcn_b, n);
    k_gemm64v3<<<nb64, 256, G64_SMEM>>>(gat_W, n);
    k_gat_node<<<nbW, 256>>>(att_s, att_d, n);
    k_gat_agg<<<nbW, 256>>>(gat_b, n);
    k_final<<<nb64, 512, FIN_SMEM>>>(H, gate_W, gate_b, res_W1, res_b1, res_W2, res_b2,
                                     sp_W1, sp_b1, sp_W2, sp_b2, delta, hf, pred, n);
}

// round 4
// speedup vs baseline: 1.2619x; 1.2619x over previous
#include <cuda_runtime.h>

#define D 64
#define NMAX 100000
#define EMAX 1600000

// ---------------- scratch (static device globals) ----------------
__device__ float g_h[NMAX * D];    // h (GCN) then h2 (GAT)
__device__ float g_x[NMAX * D];    // GCN output x, then diffused
__device__ float g_as[NMAX];
__device__ float g_ad[NMAX];
__device__ float g_dinv[NMAX];
__device__ int   g_cnt[NMAX];
__device__ int   g_rs[NMAX];
__device__ int   g_cur[NMAX];
__device__ int   g_bsum[256];
__device__ int   g_csrc[EMAX];

// ---------------- helpers ----------------
__device__ __forceinline__ float4 f4fma(float a, float4 b, float4 c) {
    c.x = fmaf(a, b.x, c.x); c.y = fmaf(a, b.y, c.y);
    c.z = fmaf(a, b.z, c.z); c.w = fmaf(a, b.w, c.w);
    return c;
}
__device__ __forceinline__ float sigmoidf_(float x) { return 1.0f / (1.0f + __expf(-x)); }

// ---------------- CSR build ----------------
__global__ void k_zero(int n) {
    int i = blockIdx.x * blockDim.x + threadIdx.x;
    if (i < n) g_cnt[i] = 0;
}
__global__ void k_cnt(const int* __restrict__ ei, int E) {
    int e = blockIdx.x * blockDim.x + threadIdx.x;
    if (e < E) atomicAdd(&g_cnt[ei[E + e]], 1);
}
__global__ void k_scanA(int n) {
    __shared__ int s[1024];
    int tid = threadIdx.x;
    int i = blockIdx.x * 1024 + tid;
    int v = (i < n) ? g_cnt[i] : 0;
    s[tid] = v; __syncthreads();
    for (int off = 1; off < 1024; off <<= 1) {
        int t = (tid >= off) ? s[tid - off] : 0;
        __syncthreads();
        s[tid] += t; __syncthreads();
    }
    if (i < n) g_rs[i] = s[tid] - v;
    if (tid == 1023) g_bsum[blockIdx.x] = s[1023];
}
__global__ void k_scanB(int nb) {
    __shared__ int s[128];
    int tid = threadIdx.x;
    int v = (tid < nb) ? g_bsum[tid] : 0;
    s[tid] = v; __syncthreads();
    for (int off = 1; off < 128; off <<= 1) {
        int t = (tid >= off) ? s[tid - off] : 0;
        __syncthreads();
        s[tid] += t; __syncthreads();
    }
    if (tid < nb) g_bsum[tid] = s[tid] - v;
}
__global__ void k_scanC(int n) {
    int i = blockIdx.x * blockDim.x + threadIdx.x;
    if (i >= n) return;
    int base = g_bsum[i >> 10];
    int r = g_rs[i] + base;
    g_rs[i] = r;
    g_cur[i] = r;
    g_dinv[i] = rsqrtf((float)g_cnt[i] + 1.0f);  // deg includes self-loop
}
__global__ void k_csr(const int* __restrict__ ei, int E) {
    int e = blockIdx.x * blockDim.x + threadIdx.x;
    if (e >= E) return;
    int s = ei[e], d = ei[E + e];
    int p = atomicAdd(&g_cur[d], 1);
    g_csrc[p] = s;
}

// ---------------- fused encoder MLP + GCN weight GEMM (64-row tile, 4 rows/thread) ----
// smem: evs[64][9] | t1[64][65] | t2[64][65] | Wb[1024] float4
__global__ void k_encgemm(const float* __restrict__ ev,
                          const float* __restrict__ W1, const float* __restrict__ b1,
                          const float* __restrict__ W2, const float* __restrict__ b2,
                          const float* __restrict__ gcnW, int n) {
    extern __shared__ float sm[];
    float* evs = sm;                    // 64*9 = 576
    float* t1  = sm + 576;              // 64*65 = 4160
    float* t2  = t1 + 4160;             // 4160
    float4* Wb = (float4*)(t2 + 4160);  // 1024 float4

    int tid = threadIdx.x;
    int c4 = tid & 15, rq = tid >> 4;
    int row0 = blockIdx.x * 64;

    for (int i = tid; i < 512; i += 256) {
        int rr = i >> 3, cc = i & 7;
        int gr = row0 + rr;
        evs[rr * 9 + cc] = (gr < n) ? ev[gr * 8 + cc] : 0.0f;
    }
    if (tid < 128) Wb[tid] = ((const float4*)W1)[tid];
    __syncthreads();

    float4 a[4];
#pragma unroll
    for (int m = 0; m < 4; m++) a[m] = ((const float4*)b1)[c4];
#pragma unroll
    for (int k = 0; k < 8; k++) {
        float4 w = Wb[k * 16 + c4];
#pragma unroll
        for (int m = 0; m < 4; m++) a[m] = f4fma(evs[(rq + 16 * m) * 9 + k], w, a[m]);
    }
#pragma unroll
    for (int m = 0; m < 4; m++) {
        int rm = rq + 16 * m;
        t1[rm * 65 + c4 * 4 + 0] = fmaxf(a[m].x, 0.f);
        t1[rm * 65 + c4 * 4 + 1] = fmaxf(a[m].y, 0.f);
        t1[rm * 65 + c4 * 4 + 2] = fmaxf(a[m].z, 0.f);
        t1[rm * 65 + c4 * 4 + 3] = fmaxf(a[m].w, 0.f);
    }
    __syncthreads();
    for (int i = tid; i < 1024; i += 256) Wb[i] = ((const float4*)W2)[i];
    __syncthreads();

#pragma unroll
    for (int m = 0; m < 4; m++) a[m] = ((const float4*)b2)[c4];
#pragma unroll 16
    for (int k = 0; k < 64; k++) {
        float4 w = Wb[k * 16 + c4];
#pragma unroll
        for (int m = 0; m < 4; m++) a[m] = f4fma(t1[(rq + 16 * m) * 65 + k], w, a[m]);
    }
#pragma unroll
    for (int m = 0; m < 4; m++) {
        int rm = rq + 16 * m;
        t2[rm * 65 + c4 * 4 + 0] = a[m].x;
        t2[rm * 65 + c4 * 4 + 1] = a[m].y;
        t2[rm * 65 + c4 * 4 + 2] = a[m].z;
        t2[rm * 65 + c4 * 4 + 3] = a[m].w;
    }
    __syncthreads();
    for (int i = tid; i < 1024; i += 256) Wb[i] = ((const float4*)gcnW)[i];
    __syncthreads();

#pragma unroll
    for (int m = 0; m < 4; m++) a[m] = make_float4(0.f, 0.f, 0.f, 0.f);
#pragma unroll 16
    for (int k = 0; k < 64; k++) {
        float4 w = Wb[k * 16 + c4];
#pragma unroll
        for (int m = 0; m < 4; m++) a[m] = f4fma(t2[(rq + 16 * m) * 65 + k], w, a[m]);
    }
#pragma unroll
    for (int m = 0; m < 4; m++) {
        int row = row0 + rq + 16 * m;
        if (row < n) ((float4*)g_h)[row * 16 + c4] = a[m];
    }
}

// ---------------- GAT weight GEMM + fused att coefficients ----------------
// g_x @ W -> g_h ; also computes g_as/g_ad per row via half-warp reduction
__global__ void k_gemm_gat(const float* __restrict__ W,
                           const float* __restrict__ att_s, const float* __restrict__ att_d,
                           int n) {
    __shared__ float Xs[64 * 65];
    __shared__ float4 Ws[1024];
    int tid = threadIdx.x;
    int c4 = tid & 15, rq = tid >> 4;
    int row0 = blockIdx.x * 64;

    for (int i = tid; i < 1024; i += 256) {
        int rr = i >> 4, cc = i & 15;
        int gr = row0 + rr;
        float4 v = make_float4(0.f, 0.f, 0.f, 0.f);
        if (gr < n) v = ((const float4*)g_x)[gr * 16 + cc];
        int base = rr * 65 + cc * 4;
        Xs[base] = v.x; Xs[base + 1] = v.y; Xs[base + 2] = v.z; Xs[base + 3] = v.w;
    }
    for (int i = tid; i < 1024; i += 256) Ws[i] = ((const float4*)W)[i];
    __syncthreads();

    float4 a[4];
#pragma unroll
    for (int m = 0; m < 4; m++) a[m] = make_float4(0.f, 0.f, 0.f, 0.f);
#pragma unroll 16
    for (int k = 0; k < 64; k++) {
        float4 w = Ws[k * 16 + c4];
#pragma unroll
        for (int m = 0; m < 4; m++) a[m] = f4fma(Xs[(rq + 16 * m) * 65 + k], w, a[m]);
    }

    float4 as4 = ((const float4*)att_s)[c4];
    float4 ad4 = ((const float4*)att_d)[c4];
#pragma unroll
    for (int m = 0; m < 4; m++) {
        int row = row0 + rq + 16 * m;
        if (row < n) ((float4*)g_h)[row * 16 + c4] = a[m];
        // per-row attention partials over this thread's 4 columns
        float ps = a[m].x * as4.x + a[m].y * as4.y + a[m].z * as4.z + a[m].w * as4.w;
        float pd = a[m].x * ad4.x + a[m].y * ad4.y + a[m].z * ad4.z + a[m].w * ad4.w;
        // reduce across the 16 lanes (same half-warp shares one row)
#pragma unroll
        for (int o = 8; o; o >>= 1) {
            ps += __shfl_xor_sync(0xffffffffu, ps, o);
            pd += __shfl_xor_sync(0xffffffffu, pd, o);
        }
        if (c4 == 0 && row < n) { g_as[row] = ps; g_ad[row] = pd; }
    }
}

// ---------------- GCN pull aggregation (warp/node, MLP-4 inner) ----------------
__global__ void k_gcn_agg(const float* __restrict__ b, int n) {
    int gt = blockIdx.x * blockDim.x + threadIdx.x;
    int d = gt >> 5, lane = gt & 31;
    if (d >= n) return;
    const float2* H2 = (const float2*)g_h;
    float dinv_d = g_dinv[d];
    float2 hv = H2[d * 32 + lane];
    float sn = dinv_d * dinv_d;
    float ax = hv.x * sn, ay = hv.y * sn;
    int beg = g_rs[d], cnt = g_cnt[d];
    for (int c0 = 0; c0 < cnt; c0 += 32) {
        int idx = c0 + lane;
        int s = 0; float nm = 0.f;
        if (idx < cnt) { s = __ldg(&g_csrc[beg + idx]); nm = g_dinv[s] * dinv_d; }
        int m = min(32, cnt - c0);
        int j = 0;
        for (; j + 4 <= m; j += 4) {
            int s0 = __shfl_sync(0xffffffffu, s, j);
            int s1 = __shfl_sync(0xffffffffu, s, j + 1);
            int s2 = __shfl_sync(0xffffffffu, s, j + 2);
            int s3 = __shfl_sync(0xffffffffu, s, j + 3);
            float n0 = __shfl_sync(0xffffffffu, nm, j);
            float n1 = __shfl_sync(0xffffffffu, nm, j + 1);
            float n2 = __shfl_sync(0xffffffffu, nm, j + 2);
            float n3 = __shfl_sync(0xffffffffu, nm, j + 3);
            float2 v0 = H2[s0 * 32 + lane];
            float2 v1 = H2[s1 * 32 + lane];
            float2 v2 = H2[s2 * 32 + lane];
            float2 v3 = H2[s3 * 32 + lane];
            ax = fmaf(n0, v0.x, ax); ay = fmaf(n0, v0.y, ay);
            ax = fmaf(n1, v1.x, ax); ay = fmaf(n1, v1.y, ay);
            ax = fmaf(n2, v2.x, ax); ay = fmaf(n2, v2.y, ay);
            ax = fmaf(n3, v3.x, ax); ay = fmaf(n3, v3.y, ay);
        }
        for (; j < m; j++) {
            int sj = __shfl_sync(0xffffffffu, s, j);
            float nj = __shfl_sync(0xffffffffu, nm, j);
            float2 v = H2[sj * 32 + lane];
            ax = fmaf(nj, v.x, ax); ay = fmaf(nj, v.y, ay);
        }
    }
    float2 bb = ((const float2*)b)[lane];
    float2 o;
    o.x = fmaxf(ax + bb.x, 0.f);
    o.y = fmaxf(ay + bb.y, 0.f);
    ((float2*)g_x)[d * 32 + lane] = o;
}

// ---------------- GAT pull aggregation (warp/node, MLP-4 inner) ----------------
__global__ void k_gat_agg(const float* __restrict__ b, int n) {
    int gt = blockIdx.x * blockDim.x + threadIdx.x;
    int d = gt >> 5, lane = gt & 31;
    if (d >= n) return;
    const float2* H2 = (const float2*)g_h;
    float ad_d = g_ad[d];
    float e0 = g_as[d] + ad_d;
    float l0 = e0 > 0.f ? e0 : 0.2f * e0;
    float wself = __expf(l0);
    float2 hd = H2[d * 32 + lane];
    float ax = wself * hd.x, ay = wself * hd.y;
    float zp = (lane == 0) ? wself : 0.f;
    int beg = g_rs[d], cnt = g_cnt[d];
    for (int c0 = 0; c0 < cnt; c0 += 32) {
        int idx = c0 + lane;
        int s = 0; float w = 0.f;
        if (idx < cnt) {
            s = __ldg(&g_csrc[beg + idx]);
            float ev = g_as[s] + ad_d;
            float lr = ev > 0.f ? ev : 0.2f * ev;
            w = __expf(lr);
        }
        zp += w;
        int m = min(32, cnt - c0);
        int j = 0;
        for (; j + 4 <= m; j += 4) {
            int s0 = __shfl_sync(0xffffffffu, s, j);
            int s1 = __shfl_sync(0xffffffffu, s, j + 1);
            int s2 = __shfl_sync(0xffffffffu, s, j + 2);
            int s3 = __shfl_sync(0xffffffffu, s, j + 3);
            float w0 = __shfl_sync(0xffffffffu, w, j);
            float w1 = __shfl_sync(0xffffffffu, w, j + 1);
            float w2 = __shfl_sync(0xffffffffu, w, j + 2);
            float w3 = __shfl_sync(0xffffffffu, w, j + 3);
            float2 v0 = H2[s0 * 32 + lane];
            float2 v1 = H2[s1 * 32 + lane];
            float2 v2 = H2[s2 * 32 + lane];
            float2 v3 = H2[s3 * 32 + lane];
            ax = fmaf(w0, v0.x, ax); ay = fmaf(w0, v0.y, ay);
            ax = fmaf(w1, v1.x, ax); ay = fmaf(w1, v1.y, ay);
            ax = fmaf(w2, v2.x, ax); ay = fmaf(w2, v2.y, ay);
            ax = fmaf(w3, v3.x, ax); ay = fmaf(w3, v3.y, ay);
        }
        for (; j < m; j++) {
            int sj = __shfl_sync(0xffffffffu, s, j);
            float wj = __shfl_sync(0xffffffffu, w, j);
            float2 v = H2[sj * 32 + lane];
            ax = fmaf(wj, v.x, ax); ay = fmaf(wj, v.y, ay);
        }
    }
#pragma unroll
    for (int o = 16; o; o >>= 1) zp += __shfl_xor_sync(0xffffffffu, zp, o);
    float inv = 1.0f / zp;
    float2 bb = ((const float2*)b)[lane];
    float2 o2;
    o2.x = fmaxf(fmaf(ax, inv, bb.x), 0.f);
    o2.y = fmaxf(fmaf(ay, inv, bb.y), 0.f);
    ((float2*)g_x)[d * 32 + lane] = o2;
}

// ---------------- fused gate + residual + speed head (64-row tile, 4 rows/thread) ----
// dyn smem: fus[64][129] | Wb 2048 float4 | gb[64][65] | tb[64][65]
__global__ void k_final(const float* __restrict__ H,
                        const float* __restrict__ gate_W, const float* __restrict__ gate_b,
                        const float* __restrict__ res_W1, const float* __restrict__ res_b1,
                        const float* __restrict__ res_W2, const float* __restrict__ res_b2,
                        const float* __restrict__ sp_W1, const float* __restrict__ sp_b1,
                        const float* __restrict__ sp_W2, const float* __restrict__ sp_b2,
                        float* __restrict__ delta_out, float* __restrict__ hf_out,
                        float* __restrict__ pred_out, int n) {
    extern __shared__ float sm[];
    float* fus = sm;                          // 64*129 = 8256
    float* gb  = sm + 8256;                   // 64*65 = 4160
    float* tb  = gb + 4160;                   // 4160
    float4* Wb = (float4*)(tb + 4160);        // 2048 float4

    int tid = threadIdx.x;
    int c4 = tid & 15, rq = tid >> 4;
    int row0 = blockIdx.x * 64;

    for (int i = tid; i < 2048; i += 256) {
        int rr = i >> 5, j = i & 31;
        int gr = row0 + rr;
        float4 v = make_float4(0.f, 0.f, 0.f, 0.f);
        if (gr < n) v = (j < 16) ? ((const float4*)H)[gr * 16 + j]
                                 : ((const float4*)g_x)[gr * 16 + (j - 16)];
        int base = rr * 129 + j * 4;
        fus[base] = v.x; fus[base + 1] = v.y; fus[base + 2] = v.z; fus[base + 3] = v.w;
    }
    for (int i = tid; i < 2048; i += 256) Wb[i] = ((const float4*)gate_W)[i];
    __syncthreads();

    float4 a[4];
    // gate
#pragma unroll
    for (int m = 0; m < 4; m++) a[m] = ((const float4*)gate_b)[c4];
#pragma unroll 16
    for (int k = 0; k < 128; k++) {
        float4 w = Wb[k * 16 + c4];
#pragma unroll
        for (int m = 0; m < 4; m++) a[m] = f4fma(fus[(rq + 16 * m) * 129 + k], w, a[m]);
    }
#pragma unroll
    for (int m = 0; m < 4; m++) {
        int rm = rq + 16 * m;
        gb[rm * 65 + c4 * 4 + 0] = sigmoidf_(a[m].x);
        gb[rm * 65 + c4 * 4 + 1] = sigmoidf_(a[m].y);
        gb[rm * 65 + c4 * 4 + 2] = sigmoidf_(a[m].z);
        gb[rm * 65 + c4 * 4 + 3] = sigmoidf_(a[m].w);
    }
    __syncthreads();
    for (int i = tid; i < 2048; i += 256) Wb[i] = ((const float4*)res_W1)[i];
    __syncthreads();

    // res layer 1
#pragma unroll
    for (int m = 0; m < 4; m++) a[m] = ((const float4*)res_b1)[c4];
#pragma unroll 16
    for (int k = 0; k < 128; k++) {
        float4 w = Wb[k * 16 + c4];
#pragma unroll
        for (int m = 0; m < 4; m++) a[m] = f4fma(fus[(rq + 16 * m) * 129 + k], w, a[m]);
    }
#pragma unroll
    for (int m = 0; m < 4; m++) {
        int rm = rq + 16 * m;
        tb[rm * 65 + c4 * 4 + 0] = fmaxf(a[m].x, 0.f);
        tb[rm * 65 + c4 * 4 + 1] = fmaxf(a[m].y, 0.f);
        tb[rm * 65 + c4 * 4 + 2] = fmaxf(a[m].z, 0.f);
        tb[rm * 65 + c4 * 4 + 3] = fmaxf(a[m].w, 0.f);
    }
    __syncthreads();
    for (int i = tid; i < 1024; i += 256) Wb[i] = ((const float4*)res_W2)[i];
    __syncthreads();

    // res layer 2 + delta + H_final
#pragma unroll
    for (int m = 0; m < 4; m++) a[m] = ((const float4*)res_b2)[c4];
#pragma unroll 16
    for (int k = 0; k < 64; k++) {
        float4 w = Wb[k * 16 + c4];
#pragma unroll
        for (int m = 0; m < 4; m++) a[m] = f4fma(tb[(rq + 16 * m) * 65 + k], w, a[m]);
    }
#pragma unroll
    for (int m = 0; m < 4; m++) {
        int rm = rq + 16 * m;
        int row = row0 + rm;
        float g0 = gb[rm * 65 + c4 * 4 + 0], g1 = gb[rm * 65 + c4 * 4 + 1];
        float g2 = gb[rm * 65 + c4 * 4 + 2], g3 = gb[rm * 65 + c4 * 4 + 3];
        float h0 = fus[rm * 129 + c4 * 4 + 0], h1 = fus[rm * 129 + c4 * 4 + 1];
        float h2 = fus[rm * 129 + c4 * 4 + 2], h3 = fus[rm * 129 + c4 * 4 + 3];
        float4 d4 = make_float4(g0 * a[m].x, g1 * a[m].y, g2 * a[m].z, g3 * a[m].w);
        float4 hf4 = make_float4(h0 + d4.x, h1 + d4.y, h2 + d4.z, h3 + d4.w);
        if (row < n) {
            ((float4*)delta_out)[row * 16 + c4] = d4;
            ((float4*)hf_out)[row * 16 + c4] = hf4;
        }
        gb[rm * 65 + c4 * 4 + 0] = hf4.x;
        gb[rm * 65 + c4 * 4 + 1] = hf4.y;
        gb[rm * 65 + c4 * 4 + 2] = hf4.z;
        gb[rm * 65 + c4 * 4 + 3] = hf4.w;
    }
    __syncthreads();
    for (int i = tid; i < 512; i += 256) Wb[i] = ((const float4*)sp_W1)[i];
    __syncthreads();

    // speed head layer 1: cols c4*2, c4*2+1
    {
        const float* Wf = (const float*)Wb;
        float s0[4], s1[4];
#pragma unroll
        for (int m = 0; m < 4; m++) { s0[m] = sp_b1[c4 * 2]; s1[m] = sp_b1[c4 * 2 + 1]; }
#pragma unroll 8
        for (int k = 0; k < 64; k++) {
            float w0 = Wf[k * 32 + c4 * 2], w1 = Wf[k * 32 + c4 * 2 + 1];
#pragma unroll
            for (int m = 0; m < 4; m++) {
                float hv = gb[(rq + 16 * m) * 65 + k];
                s0[m] = fmaf(hv, w0, s0[m]);
                s1[m] = fmaf(hv, w1, s1[m]);
            }
        }
#pragma unroll
        for (int m = 0; m < 4; m++) {
            int rm = rq + 16 * m;
            tb[rm * 65 + c4 * 2] = fmaxf(s0[m], 0.f);
            tb[rm * 65 + c4 * 2 + 1] = fmaxf(s1[m], 0.f);
        }
    }
    __syncthreads();
    if (tid < 64) {
        int gr = row0 + tid;
        if (gr < n) {
            float acc = sp_b2[0];
#pragma unroll
            for (int k = 0; k < 32; k++) acc = fmaf(tb[tid * 65 + k], sp_W2[k], acc);
            pred_out[gr] = acc;
        }
    }
}

// ---------------- launch ----------------
extern "C" void kernel_launch(void* const* d_in, const int* in_sizes, int n_in,
                              void* d_out, int out_size) {
    const float* H      = (const float*)d_in[0];
    const float* ev     = (const float*)d_in[1];
    const int*   ei     = (const int*)d_in[2];
    const float* enc_W1 = (const float*)d_in[3];
    const float* enc_b1 = (const float*)d_in[4];
    const float* enc_W2 = (const float*)d_in[5];
    const float* enc_b2 = (const float*)d_in[6];
    const float* gcn_W  = (const float*)d_in[7];
    const float* gcn_b  = (const float*)d_in[8];
    const float* gat_W  = (const float*)d_in[9];
    const float* att_s  = (const float*)d_in[10];
    const float* att_d  = (const float*)d_in[11];
    const float* gat_b  = (const float*)d_in[12];
    const float* gate_W = (const float*)d_in[13];
    const float* gate_b = (const float*)d_in[14];
    const float* res_W1 = (const float*)d_in[15];
    const float* res_b1 = (const float*)d_in[16];
    const float* res_W2 = (const float*)d_in[17];
    const float* res_b2 = (const float*)d_in[18];
    const float* sp_W1  = (const float*)d_in[19];
    const float* sp_b1  = (const float*)d_in[20];
    const float* sp_W2  = (const float*)d_in[21];
    const float* sp_b2  = (const float*)d_in[22];

    int n = in_sizes[0] / 64;
    int E = in_sizes[2] / 2;

    float* delta = (float*)d_out;
    float* hf    = delta + (size_t)n * 64;
    float* pred  = hf + (size_t)n * 64;

    int nb64   = (n + 63) / 64;
    int nbN    = (n + 255) / 256;
    int nbE    = (E + 255) / 256;
    int nb1024 = (n + 1023) / 1024;
    int nbW    = (n * 32 + 255) / 256;

    const int ENC_SMEM = (576 + 4160 + 4160) * 4 + 1024 * 16;  // 51968
    const int FIN_SMEM = (8256 + 4160 + 4160) * 4 + 2048 * 16; // 99072
    cudaFuncSetAttribute(k_encgemm, cudaFuncAttributeMaxDynamicSharedMemorySize, ENC_SMEM);
    cudaFuncSetAttribute(k_final, cudaFuncAttributeMaxDynamicSharedMemorySize, FIN_SMEM);

    k_zero<<<nbN, 256>>>(n);
    k_cnt<<<nbE, 256>>>(ei, E);
    k_scanA<<<nb1024, 1024>>>(n);
    k_scanB<<<1, 128>>>(nb1024);
    k_scanC<<<nbN, 256>>>(n);
    k_csr<<<nbE, 256>>>(ei, E);
    k_encgemm<<<nb64, 256, ENC_SMEM>>>(ev, enc_W1, enc_b1, enc_W2, enc_b2, gcn_W, n);
    k_gcn_agg<<<nbW, 256>>>(gcn_b, n);
    k_gemm_gat<<<nb64, 256>>>(gat_W, att_s, att_d, n);
    k_gat_agg<<<nbW, 256>>>(gat_b, n);
    k_final<<<nb64, 256, FIN_SMEM>>>(H, gate_W, gate_b, res_W1, res_b1, res_W2, res_b2,
                                     sp_W1, sp_b1, sp_W2, sp_b2, delta, hf, pred, n);
}

// round 5
// speedup vs baseline: 1.3734x; 1.0884x over previous
#include <cuda_runtime.h>

#define D 64
#define NMAX 100000
#define EMAX 1600000

typedef unsigned long long u64;

// ---------------- scratch (static device globals) ----------------
__device__ float g_h[NMAX * D];    // h (GCN) then h2 (GAT)
__device__ float g_x[NMAX * D];    // GCN output x, then diffused
__device__ float g_as[NMAX];
__device__ float g_ad[NMAX];
__device__ float g_dinv[NMAX];
__device__ int   g_cnt[NMAX];
__device__ int   g_rs[NMAX];
__device__ int   g_cur[NMAX];
__device__ int   g_bsum[256];
__device__ int   g_csrc[EMAX];

// ---------------- helpers ----------------
__device__ __forceinline__ float4 f4fma(float a, float4 b, float4 c) {
    c.x = fmaf(a, b.x, c.x); c.y = fmaf(a, b.y, c.y);
    c.z = fmaf(a, b.z, c.z); c.w = fmaf(a, b.w, c.w);
    return c;
}
__device__ __forceinline__ void fma2(u64& acc, u64 a, u64 b) {
    asm("fma.rn.f32x2 %0, %1, %2, %0;" : "+l"(acc) : "l"(a), "l"(b));
}
__device__ __forceinline__ u64 pack2(float lo, float hi) {
    u64 d; asm("mov.b64 %0, {%1, %2};" : "=l"(d) : "f"(lo), "f"(hi)); return d;
}
__device__ __forceinline__ float2 unpack2(u64 v) {
    float2 r; asm("mov.b64 {%0, %1}, %2;" : "=f"(r.x), "=f"(r.y) : "l"(v)); return r;
}
__device__ __forceinline__ float sigmoidf_(float x) { return 1.0f / (1.0f + __expf(-x)); }

// ---------------- CSR build ----------------
__global__ void k_zero(int n) {
    int i = blockIdx.x * blockDim.x + threadIdx.x;
    if (i < n) g_cnt[i] = 0;
}
__global__ void k_cnt(const int* __restrict__ ei, int E) {
    int e = blockIdx.x * blockDim.x + threadIdx.x;
    if (e < E) atomicAdd(&g_cnt[ei[E + e]], 1);
}
__global__ void k_scanA(int n) {
    __shared__ int s[1024];
    int tid = threadIdx.x;
    int i = blockIdx.x * 1024 + tid;
    int v = (i < n) ? g_cnt[i] : 0;
    s[tid] = v; __syncthreads();
    for (int off = 1; off < 1024; off <<= 1) {
        int t = (tid >= off) ? s[tid - off] : 0;
        __syncthreads();
        s[tid] += t; __syncthreads();
    }
    if (i < n) g_rs[i] = s[tid] - v;
    if (tid == 1023) g_bsum[blockIdx.x] = s[1023];
}
__global__ void k_scanB(int nb) {
    __shared__ int s[128];
    int tid = threadIdx.x;
    int v = (tid < nb) ? g_bsum[tid] : 0;
    s[tid] = v; __syncthreads();
    for (int off = 1; off < 128; off <<= 1) {
        int t = (tid >= off) ? s[tid - off] : 0;
        __syncthreads();
        s[tid] += t; __syncthreads();
    }
    if (tid < nb) g_bsum[tid] = s[tid] - v;
}
__global__ void k_scanC(int n) {
    int i = blockIdx.x * blockDim.x + threadIdx.x;
    if (i >= n) return;
    int base = g_bsum[i >> 10];
    int r = g_rs[i] + base;
    g_rs[i] = r;
    g_cur[i] = r;
    g_dinv[i] = rsqrtf((float)g_cnt[i] + 1.0f);  // deg includes self-loop
}
__global__ void k_csr(const int* __restrict__ ei, int E) {
    int e = blockIdx.x * blockDim.x + threadIdx.x;
    if (e >= E) return;
    int s = ei[e], d = ei[E + e];
    int p = atomicAdd(&g_cur[d], 1);
    g_csrc[p] = s;
}

// ---------------- fused encoder MLP + GCN weight GEMM (64-row tile, 4 rows/thread) ----
__global__ void k_encgemm(const float* __restrict__ ev,
                          const float* __restrict__ W1, const float* __restrict__ b1,
                          const float* __restrict__ W2, const float* __restrict__ b2,
                          const float* __restrict__ gcnW, int n) {
    extern __shared__ float sm[];
    float* evs = sm;                    // 64*9 = 576
    float* t1  = sm + 576;              // 64*65 = 4160
    float* t2  = t1 + 4160;             // 4160
    float4* Wb = (float4*)(t2 + 4160);  // 1024 float4

    int tid = threadIdx.x;
    int c4 = tid & 15, rq = tid >> 4;
    int row0 = blockIdx.x * 64;

    for (int i = tid; i < 512; i += 256) {
        int rr = i >> 3, cc = i & 7;
        int gr = row0 + rr;
        evs[rr * 9 + cc] = (gr < n) ? ev[gr * 8 + cc] : 0.0f;
    }
    if (tid < 128) Wb[tid] = ((const float4*)W1)[tid];
    __syncthreads();

    float4 a[4];
#pragma unroll
    for (int m = 0; m < 4; m++) a[m] = ((const float4*)b1)[c4];
#pragma unroll
    for (int k = 0; k < 8; k++) {
        float4 w = Wb[k * 16 + c4];
#pragma unroll
        for (int m = 0; m < 4; m++) a[m] = f4fma(evs[(rq + 16 * m) * 9 + k], w, a[m]);
    }
#pragma unroll
    for (int m = 0; m < 4; m++) {
        int rm = rq + 16 * m;
        t1[rm * 65 + c4 * 4 + 0] = fmaxf(a[m].x, 0.f);
        t1[rm * 65 + c4 * 4 + 1] = fmaxf(a[m].y, 0.f);
        t1[rm * 65 + c4 * 4 + 2] = fmaxf(a[m].z, 0.f);
        t1[rm * 65 + c4 * 4 + 3] = fmaxf(a[m].w, 0.f);
    }
    __syncthreads();
    for (int i = tid; i < 1024; i += 256) Wb[i] = ((const float4*)W2)[i];
    __syncthreads();

#pragma unroll
    for (int m = 0; m < 4; m++) a[m] = ((const float4*)b2)[c4];
#pragma unroll 16
    for (int k = 0; k < 64; k++) {
        float4 w = Wb[k * 16 + c4];
#pragma unroll
        for (int m = 0; m < 4; m++) a[m] = f4fma(t1[(rq + 16 * m) * 65 + k], w, a[m]);
    }
#pragma unroll
    for (int m = 0; m < 4; m++) {
        int rm = rq + 16 * m;
        t2[rm * 65 + c4 * 4 + 0] = a[m].x;
        t2[rm * 65 + c4 * 4 + 1] = a[m].y;
        t2[rm * 65 + c4 * 4 + 2] = a[m].z;
        t2[rm * 65 + c4 * 4 + 3] = a[m].w;
    }
    __syncthreads();
    for (int i = tid; i < 1024; i += 256) Wb[i] = ((const float4*)gcnW)[i];
    __syncthreads();

#pragma unroll
    for (int m = 0; m < 4; m++) a[m] = make_float4(0.f, 0.f, 0.f, 0.f);
#pragma unroll 16
    for (int k = 0; k < 64; k++) {
        float4 w = Wb[k * 16 + c4];
#pragma unroll
        for (int m = 0; m < 4; m++) a[m] = f4fma(t2[(rq + 16 * m) * 65 + k], w, a[m]);
    }
#pragma unroll
    for (int m = 0; m < 4; m++) {
        int row = row0 + rq + 16 * m;
        if (row < n) ((float4*)g_h)[row * 16 + c4] = a[m];
    }
}

// ---------------- GAT weight GEMM + fused att coefficients ----------------
__global__ void k_gemm_gat(const float* __restrict__ W,
                           const float* __restrict__ att_s, const float* __restrict__ att_d,
                           int n) {
    __shared__ float Xs[64 * 65];
    __shared__ float4 Ws[1024];
    int tid = threadIdx.x;
    int c4 = tid & 15, rq = tid >> 4;
    int row0 = blockIdx.x * 64;

    for (int i = tid; i < 1024; i += 256) {
        int rr = i >> 4, cc = i & 15;
        int gr = row0 + rr;
        float4 v = make_float4(0.f, 0.f, 0.f, 0.f);
        if (gr < n) v = ((const float4*)g_x)[gr * 16 + cc];
        int base = rr * 65 + cc * 4;
        Xs[base] = v.x; Xs[base + 1] = v.y; Xs[base + 2] = v.z; Xs[base + 3] = v.w;
    }
    for (int i = tid; i < 1024; i += 256) Ws[i] = ((const float4*)W)[i];
    __syncthreads();

    float4 a[4];
#pragma unroll
    for (int m = 0; m < 4; m++) a[m] = make_float4(0.f, 0.f, 0.f, 0.f);
#pragma unroll 16
    for (int k = 0; k < 64; k++) {
        float4 w = Ws[k * 16 + c4];
#pragma unroll
        for (int m = 0; m < 4; m++) a[m] = f4fma(Xs[(rq + 16 * m) * 65 + k], w, a[m]);
    }

    float4 as4 = ((const float4*)att_s)[c4];
    float4 ad4 = ((const float4*)att_d)[c4];
#pragma unroll
    for (int m = 0; m < 4; m++) {
        int row = row0 + rq + 16 * m;
        if (row < n) ((float4*)g_h)[row * 16 + c4] = a[m];
        float ps = a[m].x * as4.x + a[m].y * as4.y + a[m].z * as4.z + a[m].w * as4.w;
        float pd = a[m].x * ad4.x + a[m].y * ad4.y + a[m].z * ad4.z + a[m].w * ad4.w;
#pragma unroll
        for (int o = 8; o; o >>= 1) {
            ps += __shfl_xor_sync(0xffffffffu, ps, o);
            pd += __shfl_xor_sync(0xffffffffu, pd, o);
        }
        if (c4 == 0 && row < n) { g_as[row] = ps; g_ad[row] = pd; }
    }
}

// ---------------- GCN pull aggregation (warp/node) ----------------
__global__ void k_gcn_agg(const float* __restrict__ b, int n) {
    int gt = blockIdx.x * blockDim.x + threadIdx.x;
    int d = gt >> 5, lane = gt & 31;
    if (d >= n) return;
    const float2* H2 = (const float2*)g_h;
    float dinv_d = g_dinv[d];
    float2 hv = H2[d * 32 + lane];
    float sn = dinv_d * dinv_d;
    float ax = hv.x * sn, ay = hv.y * sn;
    int beg = g_rs[d], cnt = g_cnt[d];
    for (int c0 = 0; c0 < cnt; c0 += 32) {
        int idx = c0 + lane;
        int s = 0; float nm = 0.f;
        if (idx < cnt) { s = __ldg(&g_csrc[beg + idx]); nm = g_dinv[s] * dinv_d; }
        int m = min(32, cnt - c0);
        int j = 0;
        for (; j + 4 <= m; j += 4) {
            int s0 = __shfl_sync(0xffffffffu, s, j);
            int s1 = __shfl_sync(0xffffffffu, s, j + 1);
            int s2 = __shfl_sync(0xffffffffu, s, j + 2);
            int s3 = __shfl_sync(0xffffffffu, s, j + 3);
            float n0 = __shfl_sync(0xffffffffu, nm, j);
            float n1 = __shfl_sync(0xffffffffu, nm, j + 1);
            float n2 = __shfl_sync(0xffffffffu, nm, j + 2);
            float n3 = __shfl_sync(0xffffffffu, nm, j + 3);
            float2 v0 = H2[s0 * 32 + lane];
            float2 v1 = H2[s1 * 32 + lane];
            float2 v2 = H2[s2 * 32 + lane];
            float2 v3 = H2[s3 * 32 + lane];
            ax = fmaf(n0, v0.x, ax); ay = fmaf(n0, v0.y, ay);
            ax = fmaf(n1, v1.x, ax); ay = fmaf(n1, v1.y, ay);
            ax = fmaf(n2, v2.x, ax); ay = fmaf(n2, v2.y, ay);
            ax = fmaf(n3, v3.x, ax); ay = fmaf(n3, v3.y, ay);
        }
        for (; j < m; j++) {
            int sj = __shfl_sync(0xffffffffu, s, j);
            float nj = __shfl_sync(0xffffffffu, nm, j);
            float2 v = H2[sj * 32 + lane];
            ax = fmaf(nj, v.x, ax); ay = fmaf(nj, v.y, ay);
        }
    }
    float2 bb = ((const float2*)b)[lane];
    float2 o;
    o.x = fmaxf(ax + bb.x, 0.f);
    o.y = fmaxf(ay + bb.y, 0.f);
    ((float2*)g_x)[d * 32 + lane] = o;
}

// ---------------- GAT pull aggregation (warp/node) ----------------
__global__ void k_gat_agg(const float* __restrict__ b, int n) {
    int gt = blockIdx.x * blockDim.x + threadIdx.x;
    int d = gt >> 5, lane = gt & 31;
    if (d >= n) return;
    const float2* H2 = (const float2*)g_h;
    float ad_d = g_ad[d];
    float e0 = g_as[d] + ad_d;
    float l0 = e0 > 0.f ? e0 : 0.2f * e0;
    float wself = __expf(l0);
    float2 hd = H2[d * 32 + lane];
    float ax = wself * hd.x, ay = wself * hd.y;
    float zp = (lane == 0) ? wself : 0.f;
    int beg = g_rs[d], cnt = g_cnt[d];
    for (int c0 = 0; c0 < cnt; c0 += 32) {
        int idx = c0 + lane;
        int s = 0; float w = 0.f;
        if (idx < cnt) {
            s = __ldg(&g_csrc[beg + idx]);
            float ev = g_as[s] + ad_d;
            float lr = ev > 0.f ? ev : 0.2f * ev;
            w = __expf(lr);
        }
        zp += w;
        int m = min(32, cnt - c0);
        int j = 0;
        for (; j + 4 <= m; j += 4) {
            int s0 = __shfl_sync(0xffffffffu, s, j);
            int s1 = __shfl_sync(0xffffffffu, s, j + 1);
            int s2 = __shfl_sync(0xffffffffu, s, j + 2);
            int s3 = __shfl_sync(0xffffffffu, s, j + 3);
            float w0 = __shfl_sync(0xffffffffu, w, j);
            float w1 = __shfl_sync(0xffffffffu, w, j + 1);
            float w2 = __shfl_sync(0xffffffffu, w, j + 2);
            float w3 = __shfl_sync(0xffffffffu, w, j + 3);
            float2 v0 = H2[s0 * 32 + lane];
            float2 v1 = H2[s1 * 32 + lane];
            float2 v2 = H2[s2 * 32 + lane];
            float2 v3 = H2[s3 * 32 + lane];
            ax = fmaf(w0, v0.x, ax); ay = fmaf(w0, v0.y, ay);
            ax = fmaf(w1, v1.x, ax); ay = fmaf(w1, v1.y, ay);
            ax = fmaf(w2, v2.x, ax); ay = fmaf(w2, v2.y, ay);
            ax = fmaf(w3, v3.x, ax); ay = fmaf(w3, v3.y, ay);
        }
        for (; j < m; j++) {
            int sj = __shfl_sync(0xffffffffu, s, j);
            float wj = __shfl_sync(0xffffffffu, w, j);
            float2 v = H2[sj * 32 + lane];
            ax = fmaf(wj, v.x, ax); ay = fmaf(wj, v.y, ay);
        }
    }
#pragma unroll
    for (int o = 16; o; o >>= 1) zp += __shfl_xor_sync(0xffffffffu, zp, o);
    float inv = 1.0f / zp;
    float2 bb = ((const float2*)b)[lane];
    float2 o2;
    o2.x = fmaxf(fmaf(ax, inv, bb.x), 0.f);
    o2.y = fmaxf(fmaf(ay, inv, bb.y), 0.f);
    ((float2*)g_x)[d * 32 + lane] = o2;
}

// ---------------- fused gate + residual + speed head (row-pair f32x2) ----------------
// thread (c4 = tid&15, rp = tid>>4): cols c4*4..+3, row pairs (2rp,2rp+1) & (+32)
// dyn smem (floats): fusT[128*66]=8448 | t1T[64*66]=4224 | tb[64*34]=2176 | Wb f4[2048]
__global__ void k_final(const float* __restrict__ H,
                        const float* __restrict__ gate_W, const float* __restrict__ gate_b,
                        const float* __restrict__ res_W1, const float* __restrict__ res_b1,
                        const float* __restrict__ res_W2, const float* __restrict__ res_b2,
                        const float* __restrict__ sp_W1, const float* __restrict__ sp_b1,
                        const float* __restrict__ sp_W2, const float* __restrict__ sp_b2,
                        float* __restrict__ delta_out, float* __restrict__ hf_out,
                        float* __restrict__ pred_out, int n) {
    extern __shared__ float sm[];
    float* fusT = sm;                         // 8448
    float* t1T  = sm + 8448;                  // 4224
    float* tb   = sm + 12672;                 // 2176
    float4* Wb  = (float4*)(sm + 14848);      // 2048 float4

    int tid = threadIdx.x;
    int c4 = tid & 15, rp = tid >> 4;
    int row0 = blockIdx.x * 64;

    // load fusion transposed: fusT[k][r], conflict-free stores (lanes span r)
    for (int i = tid; i < 2048; i += 256) {
        int rr = i & 63, j = i >> 6;     // j 0..31 (float4 col index)
        int gr = row0 + rr;
        float4 v = make_float4(0.f, 0.f, 0.f, 0.f);
        if (gr < n) v = (j < 16) ? ((const float4*)H)[gr * 16 + j]
                                 : ((const float4*)g_x)[gr * 16 + (j - 16)];
        fusT[(j * 4 + 0) * 66 + rr] = v.x;
        fusT[(j * 4 + 1) * 66 + rr] = v.y;
        fusT[(j * 4 + 2) * 66 + rr] = v.z;
        fusT[(j * 4 + 3) * 66 + rr] = v.w;
    }
    for (int i = tid; i < 2048; i += 256) Wb[i] = ((const float4*)gate_W)[i];
    __syncthreads();

    // ---- gate GEMM (acc stays in registers) ----
    u64 ga[2][4];
    {
        float4 b4 = ((const float4*)gate_b)[c4];
        ga[0][0] = ga[1][0] = pack2(b4.x, b4.x);
        ga[0][1] = ga[1][1] = pack2(b4.y, b4.y);
        ga[0][2] = ga[1][2] = pack2(b4.z, b4.z);
        ga[0][3] = ga[1][3] = pack2(b4.w, b4.w);
    }
#pragma unroll 8
    for (int k = 0; k < 128; k++) {
        u64 x0 = *(const u64*)&fusT[k * 66 + 2 * rp];
        u64 x1 = *(const u64*)&fusT[k * 66 + 2 * rp + 32];
        float4 w = Wb[k * 16 + c4];
        u64 w0 = pack2(w.x, w.x), w1 = pack2(w.y, w.y);
        u64 w2 = pack2(w.z, w.z), w3 = pack2(w.w, w.w);
        fma2(ga[0][0], x0, w0); fma2(ga[0][1], x0, w1);
        fma2(ga[0][2], x0, w2); fma2(ga[0][3], x0, w3);
        fma2(ga[1][0], x1, w0); fma2(ga[1][1], x1, w1);
        fma2(ga[1][2], x1, w2); fma2(ga[1][3], x1, w3);
    }
    float gv[2][4][2];
#pragma unroll
    for (int p = 0; p < 2; p++)
#pragma unroll
        for (int c = 0; c < 4; c++) {
            float2 v = unpack2(ga[p][c]);
            gv[p][c][0] = sigmoidf_(v.x);
            gv[p][c][1] = sigmoidf_(v.y);
        }
    __syncthreads();
    for (int i = tid; i < 2048; i += 256) Wb[i] = ((const float4*)res_W1)[i];
    __syncthreads();

    // ---- res layer 1 ----
    u64 ra[2][4];
    {
        float4 b4 = ((const float4*)res_b1)[c4];
        ra[0][0] = ra[1][0] = pack2(b4.x, b4.x);
        ra[0][1] = ra[1][1] = pack2(b4.y, b4.y);
        ra[0][2] = ra[1][2] = pack2(b4.z, b4.z);
        ra[0][3] = ra[1][3] = pack2(b4.w, b4.w);
    }
#pragma unroll 8
    for (int k = 0; k < 128; k++) {
        u64 x0 = *(const u64*)&fusT[k * 66 + 2 * rp];
        u64 x1 = *(const u64*)&fusT[k * 66 + 2 * rp + 32];
        float4 w = Wb[k * 16 + c4];
        u64 w0 = pack2(w.x, w.x), w1 = pack2(w.y, w.y);
        u64 w2 = pack2(w.z, w.z), w3 = pack2(w.w, w.w);
        fma2(ra[0][0], x0, w0); fma2(ra[0][1], x0, w1);
        fma2(ra[0][2], x0, w2); fma2(ra[0][3], x0, w3);
        fma2(ra[1][0], x1, w0); fma2(ra[1][1], x1, w1);
        fma2(ra[1][2], x1, w2); fma2(ra[1][3], x1, w3);
    }
#pragma unroll
    for (int p = 0; p < 2; p++)
#pragma unroll
        for (int c = 0; c < 4; c++) {
            float2 v = unpack2(ra[p][c]);
            *(u64*)&t1T[(c4 * 4 + c) * 66 + 2 * rp + 32 * p] =
                pack2(fmaxf(v.x, 0.f), fmaxf(v.y, 0.f));
        }
    __syncthreads();
    for (int i = tid; i < 1024; i += 256) Wb[i] = ((const float4*)res_W2)[i];
    __syncthreads();

    // ---- res layer 2 ----
    {
        float4 b4 = ((const float4*)res_b2)[c4];
        ra[0][0] = ra[1][0] = pack2(b4.x, b4.x);
        ra[0][1] = ra[1][1] = pack2(b4.y, b4.y);
        ra[0][2] = ra[1][2] = pack2(b4.z, b4.z);
        ra[0][3] = ra[1][3] = pack2(b4.w, b4.w);
    }
#pragma unroll 8
    for (int k = 0; k < 64; k++) {
        u64 x0 = *(const u64*)&t1T[k * 66 + 2 * rp];
        u64 x1 = *(const u64*)&t1T[k * 66 + 2 * rp + 32];
        float4 w = Wb[k * 16 + c4];
        u64 w0 = pack2(w.x, w.x), w1 = pack2(w.y, w.y);
        u64 w2 = pack2(w.z, w.z), w3 = pack2(w.w, w.w);
        fma2(ra[0][0], x0, w0); fma2(ra[0][1], x0, w1);
        fma2(ra[0][2], x0, w2); fma2(ra[0][3], x0, w3);
        fma2(ra[1][0], x1, w0); fma2(ra[1][1], x1, w1);
        fma2(ra[1][2], x1, w2); fma2(ra[1][3], x1, w3);
    }

    // ---- delta / H_final ----
    float hfv[2][4][2];
#pragma unroll
    for (int p = 0; p < 2; p++) {
        int r0 = 2 * rp + 32 * p;
        float d_[4][2];
#pragma unroll
        for (int c = 0; c < 4; c++) {
            float2 rv = unpack2(ra[p][c]);
            float2 hv = unpack2(*(const u64*)&fusT[(c4 * 4 + c) * 66 + r0]);
            d_[c][0] = gv[p][c][0] * rv.x;
            d_[c][1] = gv[p][c][1] * rv.y;
            hfv[p][c][0] = hv.x + d_[c][0];
            hfv[p][c][1] = hv.y + d_[c][1];
        }
#pragma unroll
        for (int e = 0; e < 2; e++) {
            int row = row0 + r0 + e;
            if (row < n) {
                ((float4*)delta_out)[row * 16 + c4] =
                    make_float4(d_[0][e], d_[1][e], d_[2][e], d_[3][e]);
                ((float4*)hf_out)[row * 16 + c4] =
                    make_float4(hfv[p][0][e], hfv[p][1][e], hfv[p][2][e], hfv[p][3][e]);
            }
        }
    }
    __syncthreads();  // t1T fully consumed; Wb fully consumed

    // store H_final transposed into t1T for the speed head
#pragma unroll
    for (int p = 0; p < 2; p++)
#pragma unroll
        for (int c = 0; c < 4; c++)
            *(u64*)&t1T[(c4 * 4 + c) * 66 + 2 * rp + 32 * p] =
                pack2(hfv[p][c][0], hfv[p][c][1]);
    for (int i = tid; i < 512; i += 256) Wb[i] = ((const float4*)sp_W1)[i];
    __syncthreads();

    // ---- speed head layer 1: cols 2*c4, 2*c4+1 ----
    {
        u64 sa[2][2];
        float2 bb = ((const float2*)sp_b1)[c4];
        sa[0][0] = sa[1][0] = pack2(bb.x, bb.x);
        sa[0][1] = sa[1][1] = pack2(bb.y, bb.y);
#pragma unroll 8
        for (int k = 0; k < 64; k++) {
            u64 x0 = *(const u64*)&t1T[k * 66 + 2 * rp];
            u64 x1 = *(const u64*)&t1T[k * 66 + 2 * rp + 32];
            float2 wv = ((const float2*)Wb)[k * 16 + c4];
            u64 w0 = pack2(wv.x, wv.x), w1 = pack2(wv.y, wv.y);
            fma2(sa[0][0], x0, w0); fma2(sa[0][1], x0, w1);
            fma2(sa[1][0], x1, w0); fma2(sa[1][1], x1, w1);
        }
#pragma unroll
        for (int p = 0; p < 2; p++) {
            int r0 = 2 * rp + 32 * p;
#pragma unroll
            for (int c = 0; c < 2; c++) {
                float2 v = unpack2(sa[p][c]);
                tb[(r0 + 0) * 34 + c4 * 2 + c] = fmaxf(v.x, 0.f);
                tb[(r0 + 1) * 34 + c4 * 2 + c] = fmaxf(v.y, 0.f);
            }
        }
    }
    __syncthreads();
    if (tid < 64) {
        int gr = row0 + tid;
        if (gr < n) {
            float acc = sp_b2[0];
#pragma unroll
            for (int k = 0; k < 32; k++) acc = fmaf(tb[tid * 34 + k], sp_W2[k], acc);
            pred_out[gr] = acc;
        }
    }
}

// ---------------- launch ----------------
extern "C" void kernel_launch(void* const* d_in, const int* in_sizes, int n_in,
                              void* d_out, int out_size) {
    const float* H      = (const float*)d_in[0];
    const float* ev     = (const float*)d_in[1];
    const int*   ei     = (const int*)d_in[2];
    const float* enc_W1 = (const float*)d_in[3];
    const float* enc_b1 = (const float*)d_in[4];
    const float* enc_W2 = (const float*)d_in[5];
    const float* enc_b2 = (const float*)d_in[6];
    const float* gcn_W  = (const float*)d_in[7];
    const float* gcn_b  = (const float*)d_in[8];
    const float* gat_W  = (const float*)d_in[9];
    const float* att_s  = (const float*)d_in[10];
    const float* att_d  = (const float*)d_in[11];
    const float* gat_b  = (const float*)d_in[12];
    const float* gate_W = (const float*)d_in[13];
    const float* gate_b = (const float*)d_in[14];
    const float* res_W1 = (const float*)d_in[15];
    const float* res_b1 = (const float*)d_in[16];
    const float* res_W2 = (const float*)d_in[17];
    const float* res_b2 = (const float*)d_in[18];
    const float* sp_W1  = (const float*)d_in[19];
    const float* sp_b1  = (const float*)d_in[20];
    const float* sp_W2  = (const float*)d_in[21];
    const float* sp_b2  = (const float*)d_in[22];

    int n = in_sizes[0] / 64;
    int E = in_sizes[2] / 2;

    float* delta = (float*)d_out;
    float* hf    = delta + (size_t)n * 64;
    float* pred  = hf + (size_t)n * 64;

    int nb64   = (n + 63) / 64;
    int nbN    = (n + 255) / 256;
    int nbE    = (E + 255) / 256;
    int nb1024 = (n + 1023) / 1024;
    int nbW    = (n * 32 + 255) / 256;

    const int ENC_SMEM = (576 + 4160 + 4160) * 4 + 1024 * 16;   // 51968
    const int FIN_SMEM = (8448 + 4224 + 2176) * 4 + 2048 * 16;  // 92160
    cudaFuncSetAttribute(k_encgemm, cudaFuncAttributeMaxDynamicSharedMemorySize, ENC_SMEM);
    cudaFuncSetAttribute(k_final, cudaFuncAttributeMaxDynamicSharedMemorySize, FIN_SMEM);

    // order chosen so k_encgemm lands in ncu's profiled slot (4th launch)
    k_zero<<<nbN, 256>>>(n);
    k_cnt<<<nbE, 256>>>(ei, E);
    k_scanA<<<nb1024, 1024>>>(n);
    k_encgemm<<<nb64, 256, ENC_SMEM>>>(ev, enc_W1, enc_b1, enc_W2, enc_b2, gcn_W, n);
    k_scanB<<<1, 128>>>(nb1024);
    k_scanC<<<nbN, 256>>>(n);
    k_csr<<<nbE, 256>>>(ei, E);
    k_gcn_agg<<<nbW, 256>>>(gcn_b, n);
    k_gemm_gat<<<nb64, 256>>>(gat_W, att_s, att_d, n);
    k_gat_agg<<<nbW, 256>>>(gat_b, n);
    k_final<<<nb64, 256, FIN_SMEM>>>(H, gate_W, gate_b, res_W1, res_b1, res_W2, res_b2,
                                     sp_W1, sp_b1, sp_W2, sp_b2, delta, hf, pred, n);
}

// round 6
// speedup vs baseline: 1.3841x; 1.0078x over previous
#include <cuda_runtime.h>

#define D 64
#define NMAX 100000
#define EMAX 1600000

typedef unsigned long long u64;

// ---------------- scratch (static device globals) ----------------
__device__ float g_h[NMAX * D];    // h (GCN) then h2 (GAT)
__device__ float g_x[NMAX * D];    // GCN output x, then diffused
__device__ float g_as[NMAX];
__device__ float g_ad[NMAX];
__device__ float g_dinv[NMAX];
__device__ int   g_cnt[NMAX];
__device__ int   g_rs[NMAX];
__device__ int   g_cur[NMAX];
__device__ int   g_bsum[256];
__device__ int   g_csrc[EMAX];

// ---------------- helpers ----------------
__device__ __forceinline__ void fma2(u64& acc, u64 a, u64 b) {
    asm("fma.rn.f32x2 %0, %1, %2, %0;" : "+l"(acc) : "l"(a), "l"(b));
}
__device__ __forceinline__ u64 pack2(float lo, float hi) {
    u64 d; asm("mov.b64 %0, {%1, %2};" : "=l"(d) : "f"(lo), "f"(hi)); return d;
}
__device__ __forceinline__ float2 unpack2(u64 v) {
    float2 r; asm("mov.b64 {%0, %1}, %2;" : "=f"(r.x), "=f"(r.y) : "l"(v)); return r;
}
__device__ __forceinline__ float sigmoidf_(float x) { return 1.0f / (1.0f + __expf(-x)); }

// ---------------- CSR build ----------------
__global__ void k_zero(int n) {
    int i = blockIdx.x * blockDim.x + threadIdx.x;
    if (i < n) g_cnt[i] = 0;
}
__global__ void k_cnt(const int* __restrict__ ei, int E) {
    int e = blockIdx.x * blockDim.x + threadIdx.x;
    if (e < E) atomicAdd(&g_cnt[ei[E + e]], 1);
}
__global__ void k_scanA(int n) {
    __shared__ int s[1024];
    int tid = threadIdx.x;
    int i = blockIdx.x * 1024 + tid;
    int v = (i < n) ? g_cnt[i] : 0;
    s[tid] = v; __syncthreads();
    for (int off = 1; off < 1024; off <<= 1) {
        int t = (tid >= off) ? s[tid - off] : 0;
        __syncthreads();
        s[tid] += t; __syncthreads();
    }
    if (i < n) g_rs[i] = s[tid] - v;
    if (tid == 1023) g_bsum[blockIdx.x] = s[1023];
}
__global__ void k_scanB(int nb) {
    __shared__ int s[128];
    int tid = threadIdx.x;
    int v = (tid < nb) ? g_bsum[tid] : 0;
    s[tid] = v; __syncthreads();
    for (int off = 1; off < 128; off <<= 1) {
        int t = (tid >= off) ? s[tid - off] : 0;
        __syncthreads();
        s[tid] += t; __syncthreads();
    }
    if (tid < nb) g_bsum[tid] = s[tid] - v;
}
__global__ void k_scanC(int n) {
    int i = blockIdx.x * blockDim.x + threadIdx.x;
    if (i >= n) return;
    int base = g_bsum[i >> 10];
    int r = g_rs[i] + base;
    g_rs[i] = r;
    g_cur[i] = r;
    g_dinv[i] = rsqrtf((float)g_cnt[i] + 1.0f);  // deg includes self-loop
}
__global__ void k_csr(const int* __restrict__ ei, int E) {
    int e = blockIdx.x * blockDim.x + threadIdx.x;
    if (e >= E) return;
    int s = ei[e], d = ei[E + e];
    int p = atomicAdd(&g_cur[d], 1);
    g_csrc[p] = s;
}

// ---------------- fused encoder MLP + GCN weight GEMM (row-pair f32x2) ----------------
// thread (c4, rp): cols c4*4..+3; row pairs (2rp,2rp+1) & (2rp+32,2rp+33)
// dyn smem (floats): evT[8*66]=528 | t1T[64*66]=4224 | t2T[64*66]=4224 | Wb f4[1024]
__global__ void k_encgemm(const float* __restrict__ ev,
                          const float* __restrict__ W1, const float* __restrict__ b1,
                          const float* __restrict__ W2, const float* __restrict__ b2,
                          const float* __restrict__ gcnW, int n) {
    extern __shared__ float sm[];
    float* evT = sm;                     // 528
    float* t1T = sm + 528;               // 4224
    float* t2T = sm + 4752;              // 4224
    float4* Wb = (float4*)(sm + 8976);   // 1024 float4

    int tid = threadIdx.x;
    int c4 = tid & 15, rp = tid >> 4;
    int row0 = blockIdx.x * 64;

    // load ev transposed (64 rows x 8 cols -> evT[k][r])
    if (tid < 128) {
        int rr = tid & 63, q = tid >> 6;  // q 0..1 (float4 within row)
        int gr = row0 + rr;
        float4 v = make_float4(0.f, 0.f, 0.f, 0.f);
        if (gr < n) v = ((const float4*)ev)[gr * 2 + q];
        evT[(q * 4 + 0) * 66 + rr] = v.x;
        evT[(q * 4 + 1) * 66 + rr] = v.y;
        evT[(q * 4 + 2) * 66 + rr] = v.z;
        evT[(q * 4 + 3) * 66 + rr] = v.w;
    }
    if (tid < 128) Wb[tid] = ((const float4*)W1)[tid];  // W1: 8x64
    __syncthreads();

    u64 a[2][4];
    // ---- stage 1: t1 = relu(ev @ W1 + b1) ----
    {
        float4 b4 = ((const float4*)b1)[c4];
        a[0][0] = a[1][0] = pack2(b4.x, b4.x);
        a[0][1] = a[1][1] = pack2(b4.y, b4.y);
        a[0][2] = a[1][2] = pack2(b4.z, b4.z);
        a[0][3] = a[1][3] = pack2(b4.w, b4.w);
    }
#pragma unroll
    for (int k = 0; k < 8; k++) {
        u64 x0 = *(const u64*)&evT[k * 66 + 2 * rp];
        u64 x1 = *(const u64*)&evT[k * 66 + 2 * rp + 32];
        float4 w = Wb[k * 16 + c4];
        u64 w0 = pack2(w.x, w.x), w1 = pack2(w.y, w.y);
        u64 w2 = pack2(w.z, w.z), w3 = pack2(w.w, w.w);
        fma2(a[0][0], x0, w0); fma2(a[0][1], x0, w1);
        fma2(a[0][2], x0, w2); fma2(a[0][3], x0, w3);
        fma2(a[1][0], x1, w0); fma2(a[1][1], x1, w1);
        fma2(a[1][2], x1, w2); fma2(a[1][3], x1, w3);
    }
#pragma unroll
    for (int p = 0; p < 2; p++)
#pragma unroll
        for (int c = 0; c < 4; c++) {
            float2 v = unpack2(a[p][c]);
            *(u64*)&t1T[(c4 * 4 + c) * 66 + 2 * rp + 32 * p] =
                pack2(fmaxf(v.x, 0.f), fmaxf(v.y, 0.f));
        }
    __syncthreads();
    for (int i = tid; i < 1024; i += 256) Wb[i] = ((const float4*)W2)[i];
    __syncthreads();

    // ---- stage 2: t2 = t1 @ W2 + b2 ----
    {
        float4 b4 = ((const float4*)b2)[c4];
        a[0][0] = a[1][0] = pack2(b4.x, b4.x);
        a[0][1] = a[1][1] = pack2(b4.y, b4.y);
        a[0][2] = a[1][2] = pack2(b4.z, b4.z);
        a[0][3] = a[1][3] = pack2(b4.w, b4.w);
    }
#pragma unroll 8
    for (int k = 0; k < 64; k++) {
        u64 x0 = *(const u64*)&t1T[k * 66 + 2 * rp];
        u64 x1 = *(const u64*)&t1T[k * 66 + 2 * rp + 32];
        float4 w = Wb[k * 16 + c4];
        u64 w0 = pack2(w.x, w.x), w1 = pack2(w.y, w.y);
        u64 w2 = pack2(w.z, w.z), w3 = pack2(w.w, w.w);
        fma2(a[0][0], x0, w0); fma2(a[0][1], x0, w1);
        fma2(a[0][2], x0, w2); fma2(a[0][3], x0, w3);
        fma2(a[1][0], x1, w0); fma2(a[1][1], x1, w1);
        fma2(a[1][2], x1, w2); fma2(a[1][3], x1, w3);
    }
#pragma unroll
    for (int p = 0; p < 2; p++)
#pragma unroll
        for (int c = 0; c < 4; c++)
            *(u64*)&t2T[(c4 * 4 + c) * 66 + 2 * rp + 32 * p] = a[p][c];
    __syncthreads();
    for (int i = tid; i < 1024; i += 256) Wb[i] = ((const float4*)gcnW)[i];
    __syncthreads();

    // ---- stage 3: h = t2 @ gcnW ----
#pragma unroll
    for (int p = 0; p < 2; p++)
#pragma unroll
        for (int c = 0; c < 4; c++) a[p][c] = 0ull;
#pragma unroll 8
    for (int k = 0; k < 64; k++) {
        u64 x0 = *(const u64*)&t2T[k * 66 + 2 * rp];
        u64 x1 = *(const u64*)&t2T[k * 66 + 2 * rp + 32];
        float4 w = Wb[k * 16 + c4];
        u64 w0 = pack2(w.x, w.x), w1 = pack2(w.y, w.y);
        u64 w2 = pack2(w.z, w.z), w3 = pack2(w.w, w.w);
        fma2(a[0][0], x0, w0); fma2(a[0][1], x0, w1);
        fma2(a[0][2], x0, w2); fma2(a[0][3], x0, w3);
        fma2(a[1][0], x1, w0); fma2(a[1][1], x1, w1);
        fma2(a[1][2], x1, w2); fma2(a[1][3], x1, w3);
    }
#pragma unroll
    for (int p = 0; p < 2; p++) {
        int r0 = 2 * rp + 32 * p;
        float2 v0 = unpack2(a[p][0]), v1 = unpack2(a[p][1]);
        float2 v2 = unpack2(a[p][2]), v3 = unpack2(a[p][3]);
        int rowA = row0 + r0, rowB = row0 + r0 + 1;
        if (rowA < n) ((float4*)g_h)[rowA * 16 + c4] = make_float4(v0.x, v1.x, v2.x, v3.x);
        if (rowB < n) ((float4*)g_h)[rowB * 16 + c4] = make_float4(v0.y, v1.y, v2.y, v3.y);
    }
}

// ---------------- GAT weight GEMM + fused att coefficients (row-pair f32x2) ----------
__global__ void k_gemm_gat(const float* __restrict__ W,
                           const float* __restrict__ att_s, const float* __restrict__ att_d,
                           int n) {
    __shared__ float xT[64 * 66];
    __shared__ float4 Ws[1024];
    int tid = threadIdx.x;
    int c4 = tid & 15, rp = tid >> 4;
    int row0 = blockIdx.x * 64;

    for (int i = tid; i < 1024; i += 256) {
        int rr = i & 63, j = i >> 6;   // j 0..15 (float4 col)
        int gr = row0 + rr;
        float4 v = make_float4(0.f, 0.f, 0.f, 0.f);
        if (gr < n) v = ((const float4*)g_x)[gr * 16 + j];
        xT[(j * 4 + 0) * 66 + rr] = v.x;
        xT[(j * 4 + 1) * 66 + rr] = v.y;
        xT[(j * 4 + 2) * 66 + rr] = v.z;
        xT[(j * 4 + 3) * 66 + rr] = v.w;
    }
    for (int i = tid; i < 1024; i += 256) Ws[i] = ((const float4*)W)[i];
    __syncthreads();

    u64 a[2][4];
#pragma unroll
    for (int p = 0; p < 2; p++)
#pragma unroll
        for (int c = 0; c < 4; c++) a[p][c] = 0ull;
#pragma unroll 8
    for (int k = 0; k < 64; k++) {
        u64 x0 = *(const u64*)&xT[k * 66 + 2 * rp];
        u64 x1 = *(const u64*)&xT[k * 66 + 2 * rp + 32];
        float4 w = Ws[k * 16 + c4];
        u64 w0 = pack2(w.x, w.x), w1 = pack2(w.y, w.y);
        u64 w2 = pack2(w.z, w.z), w3 = pack2(w.w, w.w);
        fma2(a[0][0], x0, w0); fma2(a[0][1], x0, w1);
        fma2(a[0][2], x0, w2); fma2(a[0][3], x0, w3);
        fma2(a[1][0], x1, w0); fma2(a[1][1], x1, w1);
        fma2(a[1][2], x1, w2); fma2(a[1][3], x1, w3);
    }

    float4 as4 = ((const float4*)att_s)[c4];
    float4 ad4 = ((const float4*)att_d)[c4];
#pragma unroll
    for (int p = 0; p < 2; p++) {
        int r0 = 2 * rp + 32 * p;
        float2 v0 = unpack2(a[p][0]), v1 = unpack2(a[p][1]);
        float2 v2 = unpack2(a[p][2]), v3 = unpack2(a[p][3]);
        int rowA = row0 + r0, rowB = row0 + r0 + 1;
        if (rowA < n) ((float4*)g_h)[rowA * 16 + c4] = make_float4(v0.x, v1.x, v2.x, v3.x);
        if (rowB < n) ((float4*)g_h)[rowB * 16 + c4] = make_float4(v0.y, v1.y, v2.y, v3.y);

        // packed attention partials: (even row, odd row) simultaneously
        u64 ps = 0ull, pd = 0ull;
        fma2(ps, a[p][0], pack2(as4.x, as4.x)); fma2(pd, a[p][0], pack2(ad4.x, ad4.x));
        fma2(ps, a[p][1], pack2(as4.y, as4.y)); fma2(pd, a[p][1], pack2(ad4.y, ad4.y));
        fma2(ps, a[p][2], pack2(as4.z, as4.z)); fma2(pd, a[p][2], pack2(ad4.z, ad4.z));
        fma2(ps, a[p][3], pack2(as4.w, as4.w)); fma2(pd, a[p][3], pack2(ad4.w, ad4.w));
#pragma unroll
        for (int o = 8; o; o >>= 1) {
            ps += 0;  // keep compiler from reordering the asm below oddly
            u64 tps = __shfl_xor_sync(0xffffffffu, ps, o);
            u64 tpd = __shfl_xor_sync(0xffffffffu, pd, o);
            float2 va = unpack2(ps), vb = unpack2(tps);
            ps = pack2(va.x + vb.x, va.y + vb.y);
            va = unpack2(pd); vb = unpack2(tpd);
            pd = pack2(va.x + vb.x, va.y + vb.y);
        }
        if (c4 == 0) {
            float2 vs = unpack2(ps), vd = unpack2(pd);
            if (rowA < n) { g_as[rowA] = vs.x; g_ad[rowA] = vd.x; }
            if (rowB < n) { g_as[rowB] = vs.y; g_ad[rowB] = vd.y; }
        }
    }
}

// ---------------- GCN pull aggregation (warp/node) ----------------
__global__ void k_gcn_agg(const float* __restrict__ b, int n) {
    int gt = blockIdx.x * blockDim.x + threadIdx.x;
    int d = gt >> 5, lane = gt & 31;
    if (d >= n) return;
    const float2* H2 = (const float2*)g_h;
    float dinv_d = g_dinv[d];
    float2 hv = H2[d * 32 + lane];
    float sn = dinv_d * dinv_d;
    float ax = hv.x * sn, ay = hv.y * sn;
    int beg = g_rs[d], cnt = g_cnt[d];
    for (int c0 = 0; c0 < cnt; c0 += 32) {
        int idx = c0 + lane;
        int s = 0; float nm = 0.f;
        if (idx < cnt) { s = __ldg(&g_csrc[beg + idx]); nm = g_dinv[s] * dinv_d; }
        int m = min(32, cnt - c0);
        int j = 0;
        for (; j + 4 <= m; j += 4) {
            int s0 = __shfl_sync(0xffffffffu, s, j);
            int s1 = __shfl_sync(0xffffffffu, s, j + 1);
            int s2 = __shfl_sync(0xffffffffu, s, j + 2);
            int s3 = __shfl_sync(0xffffffffu, s, j + 3);
            float n0 = __shfl_sync(0xffffffffu, nm, j);
            float n1 = __shfl_sync(0xffffffffu, nm, j + 1);
            float n2 = __shfl_sync(0xffffffffu, nm, j + 2);
            float n3 = __shfl_sync(0xffffffffu, nm, j + 3);
            float2 v0 = H2[s0 * 32 + lane];
            float2 v1 = H2[s1 * 32 + lane];
            float2 v2 = H2[s2 * 32 + lane];
            float2 v3 = H2[s3 * 32 + lane];
            ax = fmaf(n0, v0.x, ax); ay = fmaf(n0, v0.y, ay);
            ax = fmaf(n1, v1.x, ax); ay = fmaf(n1, v1.y, ay);
            ax = fmaf(n2, v2.x, ax); ay = fmaf(n2, v2.y, ay);
            ax = fmaf(n3, v3.x, ax); ay = fmaf(n3, v3.y, ay);
        }
        for (; j < m; j++) {
            int sj = __shfl_sync(0xffffffffu, s, j);
            float nj = __shfl_sync(0xffffffffu, nm, j);
            float2 v = H2[sj * 32 + lane];
            ax = fmaf(nj, v.x, ax); ay = fmaf(nj, v.y, ay);
        }
    }
    float2 bb = ((const float2*)b)[lane];
    float2 o;
    o.x = fmaxf(ax + bb.x, 0.f);
    o.y = fmaxf(ay + bb.y, 0.f);
    ((float2*)g_x)[d * 32 + lane] = o;
}

// ---------------- GAT pull aggregation (warp/node) ----------------
__global__ void k_gat_agg(const float* __restrict__ b, int n) {
    int gt = blockIdx.x * blockDim.x + threadIdx.x;
    int d = gt >> 5, lane = gt & 31;
    if (d >= n) return;
    const float2* H2 = (const float2*)g_h;
    float ad_d = g_ad[d];
    float e0 = g_as[d] + ad_d;
    float l0 = e0 > 0.f ? e0 : 0.2f * e0;
    float wself = __expf(l0);
    float2 hd = H2[d * 32 + lane];
    float ax = wself * hd.x, ay = wself * hd.y;
    float zp = (lane == 0) ? wself : 0.f;
    int beg = g_rs[d], cnt = g_cnt[d];
    for (int c0 = 0; c0 < cnt; c0 += 32) {
        int idx = c0 + lane;
        int s = 0; float w = 0.f;
        if (idx < cnt) {
            s = __ldg(&g_csrc[beg + idx]);
            float ev = g_as[s] + ad_d;
            float lr = ev > 0.f ? ev : 0.2f * ev;
            w = __expf(lr);
        }
        zp += w;
        int m = min(32, cnt - c0);
        int j = 0;
        for (; j + 4 <= m; j += 4) {
            int s0 = __shfl_sync(0xffffffffu, s, j);
            int s1 = __shfl_sync(0xffffffffu, s, j + 1);
            int s2 = __shfl_sync(0xffffffffu, s, j + 2);
            int s3 = __shfl_sync(0xffffffffu, s, j + 3);
            float w0 = __shfl_sync(0xffffffffu, w, j);
            float w1 = __shfl_sync(0xffffffffu, w, j + 1);
            float w2 = __shfl_sync(0xffffffffu, w, j + 2);
            float w3 = __shfl_sync(0xffffffffu, w, j + 3);
            float2 v0 = H2[s0 * 32 + lane];
            float2 v1 = H2[s1 * 32 + lane];
            float2 v2 = H2[s2 * 32 + lane];
            float2 v3 = H2[s3 * 32 + lane];
            ax = fmaf(w0, v0.x, ax); ay = fmaf(w0, v0.y, ay);
            ax = fmaf(w1, v1.x, ax); ay = fmaf(w1, v1.y, ay);
            ax = fmaf(w2, v2.x, ax); ay = fmaf(w2, v2.y, ay);
            ax = fmaf(w3, v3.x, ax); ay = fmaf(w3, v3.y, ay);
        }
        for (; j < m; j++) {
            int sj = __shfl_sync(0xffffffffu, s, j);
            float wj = __shfl_sync(0xffffffffu, w, j);
            float2 v = H2[sj * 32 + lane];
            ax = fmaf(wj, v.x, ax); ay = fmaf(wj, v.y, ay);
        }
    }
#pragma unroll
    for (int o = 16; o; o >>= 1) zp += __shfl_xor_sync(0xffffffffu, zp, o);
    float inv = 1.0f / zp;
    float2 bb = ((const float2*)b)[lane];
    float2 o2;
    o2.x = fmaxf(fmaf(ax, inv, bb.x), 0.f);
    o2.y = fmaxf(fmaf(ay, inv, bb.y), 0.f);
    ((float2*)g_x)[d * 32 + lane] = o2;
}

// ---------------- fused gate + residual + speed head (row-pair f32x2) ----------------
__global__ void k_final(const float* __restrict__ H,
                        const float* __restrict__ gate_W, const float* __restrict__ gate_b,
                        const float* __restrict__ res_W1, const float* __restrict__ res_b1,
                        const float* __restrict__ res_W2, const float* __restrict__ res_b2,
                        const float* __restrict__ sp_W1, const float* __restrict__ sp_b1,
                        const float* __restrict__ sp_W2, const float* __restrict__ sp_b2,
                        float* __restrict__ delta_out, float* __restrict__ hf_out,
                        float* __restrict__ pred_out, int n) {
    extern __shared__ float sm[];
    float* fusT = sm;                         // 8448
    float* t1T  = sm + 8448;                  // 4224
    float* tb   = sm + 12672;                 // 2176
    float4* Wb  = (float4*)(sm + 14848);      // 2048 float4

    int tid = threadIdx.x;
    int c4 = tid & 15, rp = tid >> 4;
    int row0 = blockIdx.x * 64;

    for (int i = tid; i < 2048; i += 256) {
        int rr = i & 63, j = i >> 6;
        int gr = row0 + rr;
        float4 v = make_float4(0.f, 0.f, 0.f, 0.f);
        if (gr < n) v = (j < 16) ? ((const float4*)H)[gr * 16 + j]
                                 : ((const float4*)g_x)[gr * 16 + (j - 16)];
        fusT[(j * 4 + 0) * 66 + rr] = v.x;
        fusT[(j * 4 + 1) * 66 + rr] = v.y;
        fusT[(j * 4 + 2) * 66 + rr] = v.z;
        fusT[(j * 4 + 3) * 66 + rr] = v.w;
    }
    for (int i = tid; i < 2048; i += 256) Wb[i] = ((const float4*)gate_W)[i];
    __syncthreads();

    u64 ga[2][4];
    {
        float4 b4 = ((const float4*)gate_b)[c4];
        ga[0][0] = ga[1][0] = pack2(b4.x, b4.x);
        ga[0][1] = ga[1][1] = pack2(b4.y, b4.y);
        ga[0][2] = ga[1][2] = pack2(b4.z, b4.z);
        ga[0][3] = ga[1][3] = pack2(b4.w, b4.w);
    }
#pragma unroll 8
    for (int k = 0; k < 128; k++) {
        u64 x0 = *(const u64*)&fusT[k * 66 + 2 * rp];
        u64 x1 = *(const u64*)&fusT[k * 66 + 2 * rp + 32];
        float4 w = Wb[k * 16 + c4];
        u64 w0 = pack2(w.x, w.x), w1 = pack2(w.y, w.y);
        u64 w2 = pack2(w.z, w.z), w3 = pack2(w.w, w.w);
        fma2(ga[0][0], x0, w0); fma2(ga[0][1], x0, w1);
        fma2(ga[0][2], x0, w2); fma2(ga[0][3], x0, w3);
        fma2(ga[1][0], x1, w0); fma2(ga[1][1], x1, w1);
        fma2(ga[1][2], x1, w2); fma2(ga[1][3], x1, w3);
    }
    float gv[2][4][2];
#pragma unroll
    for (int p = 0; p < 2; p++)
#pragma unroll
        for (int c = 0; c < 4; c++) {
            float2 v = unpack2(ga[p][c]);
            gv[p][c][0] = sigmoidf_(v.x);
            gv[p][c][1] = sigmoidf_(v.y);
        }
    __syncthreads();
    for (int i = tid; i < 2048; i += 256) Wb[i] = ((const float4*)res_W1)[i];
    __syncthreads();

    u64 ra[2][4];
    {
        float4 b4 = ((const float4*)res_b1)[c4];
        ra[0][0] = ra[1][0] = pack2(b4.x, b4.x);
        ra[0][1] = ra[1][1] = pack2(b4.y, b4.y);
        ra[0][2] = ra[1][2] = pack2(b4.z, b4.z);
        ra[0][3] = ra[1][3] = pack2(b4.w, b4.w);
    }
#pragma unroll 8
    for (int k = 0; k < 128; k++) {
        u64 x0 = *(const u64*)&fusT[k * 66 + 2 * rp];
        u64 x1 = *(const u64*)&fusT[k * 66 + 2 * rp + 32];
        float4 w = Wb[k * 16 + c4];
        u64 w0 = pack2(w.x, w.x), w1 = pack2(w.y, w.y);
        u64 w2 = pack2(w.z, w.z), w3 = pack2(w.w, w.w);
        fma2(ra[0][0], x0, w0); fma2(ra[0][1], x0, w1);
        fma2(ra[0][2], x0, w2); fma2(ra[0][3], x0, w3);
        fma2(ra[1][0], x1, w0); fma2(ra[1][1], x1, w1);
        fma2(ra[1][2], x1, w2); fma2(ra[1][3], x1, w3);
    }
#pragma unroll
    for (int p = 0; p < 2; p++)
#pragma unroll
        for (int c = 0; c < 4; c++) {
            float2 v = unpack2(ra[p][c]);
            *(u64*)&t1T[(c4 * 4 + c) * 66 + 2 * rp + 32 * p] =
                pack2(fmaxf(v.x, 0.f), fmaxf(v.y, 0.f));
        }
    __syncthreads();
    for (int i = tid; i < 1024; i += 256) Wb[i] = ((const float4*)res_W2)[i];
    __syncthreads();

    {
        float4 b4 = ((const float4*)res_b2)[c4];
        ra[0][0] = ra[1][0] = pack2(b4.x, b4.x);
        ra[0][1] = ra[1][1] = pack2(b4.y, b4.y);
        ra[0][2] = ra[1][2] = pack2(b4.z, b4.z);
        ra[0][3] = ra[1][3] = pack2(b4.w, b4.w);
    }
#pragma unroll 8
    for (int k = 0; k < 64; k++) {
        u64 x0 = *(const u64*)&t1T[k * 66 + 2 * rp];
        u64 x1 = *(const u64*)&t1T[k * 66 + 2 * rp + 32];
        float4 w = Wb[k * 16 + c4];
        u64 w0 = pack2(w.x, w.x), w1 = pack2(w.y, w.y);
        u64 w2 = pack2(w.z, w.z), w3 = pack2(w.w, w.w);
        fma2(ra[0][0], x0, w0); fma2(ra[0][1], x0, w1);
        fma2(ra[0][2], x0, w2); fma2(ra[0][3], x0, w3);
        fma2(ra[1][0], x1, w0); fma2(ra[1][1], x1, w1);
        fma2(ra[1][2], x1, w2); fma2(ra[1][3], x1, w3);
    }

    float hfv[2][4][2];
#pragma unroll
    for (int p = 0; p < 2; p++) {
        int r0 = 2 * rp + 32 * p;
        float d_[4][2];
#pragma unroll
        for (int c = 0; c < 4; c++) {
            float2 rv = unpack2(ra[p][c]);
            float2 hv = unpack2(*(const u64*)&fusT[(c4 * 4 + c) * 66 + r0]);
            d_[c][0] = gv[p][c][0] * rv.x;
            d_[c][1] = gv[p][c][1] * rv.y;
            hfv[p][c][0] = hv.x + d_[c][0];
            hfv[p][c][1] = hv.y + d_[c][1];
        }
#pragma unroll
        for (int e = 0; e < 2; e++) {
            int row = row0 + r0 + e;
            if (row < n) {
                ((float4*)delta_out)[row * 16 + c4] =
                    make_float4(d_[0][e], d_[1][e], d_[2][e], d_[3][e]);
                ((float4*)hf_out)[row * 16 + c4] =
                    make_float4(hfv[p][0][e], hfv[p][1][e], hfv[p][2][e], hfv[p][3][e]);
            }
        }
    }
    __syncthreads();

#pragma unroll
    for (int p = 0; p < 2; p++)
#pragma unroll
        for (int c = 0; c < 4; c++)
            *(u64*)&t1T[(c4 * 4 + c) * 66 + 2 * rp + 32 * p] =
                pack2(hfv[p][c][0], hfv[p][c][1]);
    for (int i = tid; i < 512; i += 256) Wb[i] = ((const float4*)sp_W1)[i];
    __syncthreads();

    {
        u64 sa[2][2];
        float2 bb = ((const float2*)sp_b1)[c4];
        sa[0][0] = sa[1][0] = pack2(bb.x, bb.x);
        sa[0][1] = sa[1][1] = pack2(bb.y, bb.y);
#pragma unroll 8
        for (int k = 0; k < 64; k++) {
            u64 x0 = *(const u64*)&t1T[k * 66 + 2 * rp];
            u64 x1 = *(const u64*)&t1T[k * 66 + 2 * rp + 32];
            float2 wv = ((const float2*)Wb)[k * 16 + c4];
            u64 w0 = pack2(wv.x, wv.x), w1 = pack2(wv.y, wv.y);
            fma2(sa[0][0], x0, w0); fma2(sa[0][1], x0, w1);
            fma2(sa[1][0], x1, w0); fma2(sa[1][1], x1, w1);
        }
#pragma unroll
        for (int p = 0; p < 2; p++) {
            int r0 = 2 * rp + 32 * p;
#pragma unroll
            for (int c = 0; c < 2; c++) {
                float2 v = unpack2(sa[p][c]);
                tb[(r0 + 0) * 34 + c4 * 2 + c] = fmaxf(v.x, 0.f);
                tb[(r0 + 1) * 34 + c4 * 2 + c] = fmaxf(v.y, 0.f);
            }
        }
    }
    __syncthreads();
    if (tid < 64) {
        int gr = row0 + tid;
        if (gr < n) {
            float acc = sp_b2[0];
#pragma unroll
            for (int k = 0; k < 32; k++) acc = fmaf(tb[tid * 34 + k], sp_W2[k], acc);
            pred_out[gr] = acc;
        }
    }
}

// ---------------- launch ----------------
extern "C" void kernel_launch(void* const* d_in, const int* in_sizes, int n_in,
                              void* d_out, int out_size) {
    const float* H      = (const float*)d_in[0];
    const float* ev     = (const float*)d_in[1];
    const int*   ei     = (const int*)d_in[2];
    const float* enc_W1 = (const float*)d_in[3];
    const float* enc_b1 = (const float*)d_in[4];
    const float* enc_W2 = (const float*)d_in[5];
    const float* enc_b2 = (const float*)d_in[6];
    const float* gcn_W  = (const float*)d_in[7];
    const float* gcn_b  = (const float*)d_in[8];
    const float* gat_W  = (const float*)d_in[9];
    const float* att_s  = (const float*)d_in[10];
    const float* att_d  = (const float*)d_in[11];
    const float* gat_b  = (const float*)d_in[12];
    const float* gate_W = (const float*)d_in[13];
    const float* gate_b = (const float*)d_in[14];
    const float* res_W1 = (const float*)d_in[15];
    const float* res_b1 = (const float*)d_in[16];
    const float* res_W2 = (const float*)d_in[17];
    const float* res_b2 = (const float*)d_in[18];
    const float* sp_W1  = (const float*)d_in[19];
    const float* sp_b1  = (const float*)d_in[20];
    const float* sp_W2  = (const float*)d_in[21];
    const float* sp_b2  = (const float*)d_in[22];

    int n = in_sizes[0] / 64;
    int E = in_sizes[2] / 2;

    float* delta = (float*)d_out;
    float* hf    = delta + (size_t)n * 64;
    float* pred  = hf + (size_t)n * 64;

    int nb64   = (n + 63) / 64;
    int nbN    = (n + 255) / 256;
    int nbE    = (E + 255) / 256;
    int nb1024 = (n + 1023) / 1024;
    int nbW    = (n * 32 + 255) / 256;

    const int ENC_SMEM = (528 + 4224 + 4224) * 4 + 1024 * 16;   // 52288
    const int FIN_SMEM = (8448 + 4224 + 2176) * 4 + 2048 * 16;  // 92160
    cudaFuncSetAttribute(k_encgemm, cudaFuncAttributeMaxDynamicSharedMemorySize, ENC_SMEM);
    cudaFuncSetAttribute(k_final, cudaFuncAttributeMaxDynamicSharedMemorySize, FIN_SMEM);

    k_zero<<<nbN, 256>>>(n);
    k_cnt<<<nbE, 256>>>(ei, E);
    k_scanA<<<nb1024, 1024>>>(n);
    k_encgemm<<<nb64, 256, ENC_SMEM>>>(ev, enc_W1, enc_b1, enc_W2, enc_b2, gcn_W, n);
    k_scanB<<<1, 128>>>(nb1024);
    k_scanC<<<nbN, 256>>>(n);
    k_csr<<<nbE, 256>>>(ei, E);
    k_gcn_agg<<<nbW, 256>>>(gcn_b, n);
    k_gemm_gat<<<nb64, 256>>>(gat_W, att_s, att_d, n);
    k_gat_agg<<<nbW, 256>>>(gat_b, n);
    k_final<<<nb64, 256, FIN_SMEM>>>(H, gate_W, gate_b, res_W1, res_b1, res_W2, res_b2,
                                     sp_W1, sp_b1, sp_W2, sp_b2, delta, hf, pred, n);
}

// round 7
// speedup vs baseline: 1.5633x; 1.1295x over previous
#include <cuda_runtime.h>

#define D 64
#define NMAX 100000
#define EMAX 1600000

typedef unsigned long long u64;

// ---------------- scratch (static device globals) ----------------
__device__ float g_h[NMAX * D];    // h (GCN) then h2 (GAT)
__device__ float g_x[NMAX * D];    // GCN output x, then diffused
__device__ float g_as[NMAX];
__device__ float g_ad[NMAX];
__device__ float g_dinv[NMAX];
__device__ int   g_cnt[NMAX];
__device__ int   g_rs[NMAX];
__device__ int   g_cur[NMAX];
__device__ int   g_bsum[256];
__device__ int   g_csrc[EMAX];

// ---------------- helpers ----------------
__device__ __forceinline__ void fma2(u64& acc, u64 a, u64 b) {
    asm("fma.rn.f32x2 %0, %1, %2, %0;" : "+l"(acc) : "l"(a), "l"(b));
}
__device__ __forceinline__ u64 pack2(float lo, float hi) {
    u64 d; asm("mov.b64 %0, {%1, %2};" : "=l"(d) : "f"(lo), "f"(hi)); return d;
}
__device__ __forceinline__ float2 unpack2(u64 v) {
    float2 r; asm("mov.b64 {%0, %1}, %2;" : "=f"(r.x), "=f"(r.y) : "l"(v)); return r;
}
__device__ __forceinline__ float sigmoidf_(float x) { return 1.0f / (1.0f + __expf(-x)); }

#define STRIDE 130  // 128-row tile + 2 pad (even, bank-shifted)

// ---------------- CSR build ----------------
__global__ void k_zero(int n) {
    int i = blockIdx.x * blockDim.x + threadIdx.x;
    if (i < n) g_cnt[i] = 0;
}
__global__ void k_cnt(const int* __restrict__ ei, int E) {
    int e = blockIdx.x * blockDim.x + threadIdx.x;
    if (e < E) atomicAdd(&g_cnt[ei[E + e]], 1);
}
__global__ void k_scanA(int n) {
    __shared__ int s[1024];
    int tid = threadIdx.x;
    int i = blockIdx.x * 1024 + tid;
    int v = (i < n) ? g_cnt[i] : 0;
    s[tid] = v; __syncthreads();
    for (int off = 1; off < 1024; off <<= 1) {
        int t = (tid >= off) ? s[tid - off] : 0;
        __syncthreads();
        s[tid] += t; __syncthreads();
    }
    if (i < n) g_rs[i] = s[tid] - v;
    if (tid == 1023) g_bsum[blockIdx.x] = s[1023];
}
__global__ void k_scanB(int nb) {
    __shared__ int s[128];
    int tid = threadIdx.x;
    int v = (tid < nb) ? g_bsum[tid] : 0;
    s[tid] = v; __syncthreads();
    for (int off = 1; off < 128; off <<= 1) {
        int t = (tid >= off) ? s[tid - off] : 0;
        __syncthreads();
        s[tid] += t; __syncthreads();
    }
    if (tid < nb) g_bsum[tid] = s[tid] - v;
}
__global__ void k_scanC(int n) {
    int i = blockIdx.x * blockDim.x + threadIdx.x;
    if (i >= n) return;
    int base = g_bsum[i >> 10];
    int r = g_rs[i] + base;
    g_rs[i] = r;
    g_cur[i] = r;
    g_dinv[i] = rsqrtf((float)g_cnt[i] + 1.0f);  // deg includes self-loop
}
__global__ void k_csr(const int* __restrict__ ei, int E) {
    int e = blockIdx.x * blockDim.x + threadIdx.x;
    if (e >= E) return;
    int s = ei[e], d = ei[E + e];
    int p = atomicAdd(&g_cur[d], 1);
    g_csrc[p] = s;
}

// ================= fused encoder MLP + GCN weight GEMM =================
// 128-row tile, thread (c4, rp): cols c4*4..+3; row pairs 2rp+32p, p=0..3
// dyn smem: evT[8*130]=1040 | t1T[64*130]=8320 (t2 aliases t1) | Wb f4[1024]
__global__ void k_encgemm(const float* __restrict__ ev,
                          const float* __restrict__ W1, const float* __restrict__ b1,
                          const float* __restrict__ W2, const float* __restrict__ b2,
                          const float* __restrict__ gcnW, int n) {
    extern __shared__ float sm[];
    float* evT = sm;                     // 1040
    float* t1T = sm + 1040;              // 8320
    float4* Wb = (float4*)(sm + 9360);   // 1024 float4

    int tid = threadIdx.x;
    int c4 = tid & 15, rp = tid >> 4;
    int row0 = blockIdx.x * 128;

    // load ev transposed (128 rows x 8 cols)
    {
        int rr = tid & 127, q = tid >> 7;
        int gr = row0 + rr;
        float4 v = make_float4(0.f, 0.f, 0.f, 0.f);
        if (gr < n) v = ((const float4*)ev)[gr * 2 + q];
        evT[(q * 4 + 0) * STRIDE + rr] = v.x;
        evT[(q * 4 + 1) * STRIDE + rr] = v.y;
        evT[(q * 4 + 2) * STRIDE + rr] = v.z;
        evT[(q * 4 + 3) * STRIDE + rr] = v.w;
    }
    if (tid < 128) Wb[tid] = ((const float4*)W1)[tid];
    __syncthreads();

    u64 a[4][4];
    // ---- stage 1: t1 = relu(ev @ W1 + b1) ----
    {
        float4 b4 = ((const float4*)b1)[c4];
        u64 i0 = pack2(b4.x, b4.x), i1 = pack2(b4.y, b4.y);
        u64 i2 = pack2(b4.z, b4.z), i3 = pack2(b4.w, b4.w);
#pragma unroll
        for (int p = 0; p < 4; p++) { a[p][0] = i0; a[p][1] = i1; a[p][2] = i2; a[p][3] = i3; }
    }
#pragma unroll
    for (int k = 0; k < 8; k++) {
        float4 w = Wb[k * 16 + c4];
        u64 w0 = pack2(w.x, w.x), w1 = pack2(w.y, w.y);
        u64 w2 = pack2(w.z, w.z), w3 = pack2(w.w, w.w);
#pragma unroll
        for (int p = 0; p < 4; p++) {
            u64 x = *(const u64*)&evT[k * STRIDE + 2 * rp + 32 * p];
            fma2(a[p][0], x, w0); fma2(a[p][1], x, w1);
            fma2(a[p][2], x, w2); fma2(a[p][3], x, w3);
        }
    }
#pragma unroll
    for (int p = 0; p < 4; p++)
#pragma unroll
        for (int c = 0; c < 4; c++) {
            float2 v = unpack2(a[p][c]);
            *(u64*)&t1T[(c4 * 4 + c) * STRIDE + 2 * rp + 32 * p] =
                pack2(fmaxf(v.x, 0.f), fmaxf(v.y, 0.f));
        }
    __syncthreads();
    for (int i = tid; i < 1024; i += 256) Wb[i] = ((const float4*)W2)[i];
    __syncthreads();

    // ---- stage 2: t2 = t1 @ W2 + b2 ----
    {
        float4 b4 = ((const float4*)b2)[c4];
        u64 i0 = pack2(b4.x, b4.x), i1 = pack2(b4.y, b4.y);
        u64 i2 = pack2(b4.z, b4.z), i3 = pack2(b4.w, b4.w);
#pragma unroll
        for (int p = 0; p < 4; p++) { a[p][0] = i0; a[p][1] = i1; a[p][2] = i2; a[p][3] = i3; }
    }
#pragma unroll 4
    for (int k = 0; k < 64; k++) {
        float4 w = Wb[k * 16 + c4];
        u64 w0 = pack2(w.x, w.x), w1 = pack2(w.y, w.y);
        u64 w2 = pack2(w.z, w.z), w3 = pack2(w.w, w.w);
#pragma unroll
        for (int p = 0; p < 4; p++) {
            u64 x = *(const u64*)&t1T[k * STRIDE + 2 * rp + 32 * p];
            fma2(a[p][0], x, w0); fma2(a[p][1], x, w1);
            fma2(a[p][2], x, w2); fma2(a[p][3], x, w3);
        }
    }
    __syncthreads();  // all reads of t1 done; safe to overwrite with t2
#pragma unroll
    for (int p = 0; p < 4; p++)
#pragma unroll
        for (int c = 0; c < 4; c++)
            *(u64*)&t1T[(c4 * 4 + c) * STRIDE + 2 * rp + 32 * p] = a[p][c];
    for (int i = tid; i < 1024; i += 256) Wb[i] = ((const float4*)gcnW)[i];
    __syncthreads();

    // ---- stage 3: h = t2 @ gcnW ----
#pragma unroll
    for (int p = 0; p < 4; p++)
#pragma unroll
        for (int c = 0; c < 4; c++) a[p][c] = 0ull;
#pragma unroll 4
    for (int k = 0; k < 64; k++) {
        float4 w = Wb[k * 16 + c4];
        u64 w0 = pack2(w.x, w.x), w1 = pack2(w.y, w.y);
        u64 w2 = pack2(w.z, w.z), w3 = pack2(w.w, w.w);
#pragma unroll
        for (int p = 0; p < 4; p++) {
            u64 x = *(const u64*)&t1T[k * STRIDE + 2 * rp + 32 * p];
            fma2(a[p][0], x, w0); fma2(a[p][1], x, w1);
            fma2(a[p][2], x, w2); fma2(a[p][3], x, w3);
        }
    }
#pragma unroll
    for (int p = 0; p < 4; p++) {
        int r0 = 2 * rp + 32 * p;
        float2 v0 = unpack2(a[p][0]), v1 = unpack2(a[p][1]);
        float2 v2 = unpack2(a[p][2]), v3 = unpack2(a[p][3]);
        int rowA = row0 + r0, rowB = rowA + 1;
        if (rowA < n) ((float4*)g_h)[rowA * 16 + c4] = make_float4(v0.x, v1.x, v2.x, v3.x);
        if (rowB < n) ((float4*)g_h)[rowB * 16 + c4] = make_float4(v0.y, v1.y, v2.y, v3.y);
    }
}

// ================= GAT weight GEMM + fused att coefficients =================
// 128-row tile; dyn smem: xT[64*130]=8320 | Ws f4[1024]
__global__ void k_gemm_gat(const float* __restrict__ W,
                           const float* __restrict__ att_s, const float* __restrict__ att_d,
                           int n) {
    extern __shared__ float sm[];
    float* xT = sm;                     // 8320
    float4* Ws = (float4*)(sm + 8320);  // 1024 float4

    int tid = threadIdx.x;
    int c4 = tid & 15, rp = tid >> 4;
    int row0 = blockIdx.x * 128;

    for (int i = tid; i < 2048; i += 256) {
        int rr = i & 127, j = i >> 7;   // j 0..15
        int gr = row0 + rr;
        float4 v = make_float4(0.f, 0.f, 0.f, 0.f);
        if (gr < n) v = ((const float4*)g_x)[gr * 16 + j];
        xT[(j * 4 + 0) * STRIDE + rr] = v.x;
        xT[(j * 4 + 1) * STRIDE + rr] = v.y;
        xT[(j * 4 + 2) * STRIDE + rr] = v.z;
        xT[(j * 4 + 3) * STRIDE + rr] = v.w;
    }
    for (int i = tid; i < 1024; i += 256) Ws[i] = ((const float4*)W)[i];
    __syncthreads();

    u64 a[4][4];
#pragma unroll
    for (int p = 0; p < 4; p++)
#pragma unroll
        for (int c = 0; c < 4; c++) a[p][c] = 0ull;
#pragma unroll 4
    for (int k = 0; k < 64; k++) {
        float4 w = Ws[k * 16 + c4];
        u64 w0 = pack2(w.x, w.x), w1 = pack2(w.y, w.y);
        u64 w2 = pack2(w.z, w.z), w3 = pack2(w.w, w.w);
#pragma unroll
        for (int p = 0; p < 4; p++) {
            u64 x = *(const u64*)&xT[k * STRIDE + 2 * rp + 32 * p];
            fma2(a[p][0], x, w0); fma2(a[p][1], x, w1);
            fma2(a[p][2], x, w2); fma2(a[p][3], x, w3);
        }
    }

    float4 as4 = ((const float4*)att_s)[c4];
    float4 ad4 = ((const float4*)att_d)[c4];
#pragma unroll
    for (int p = 0; p < 4; p++) {
        int r0 = 2 * rp + 32 * p;
        float2 v0 = unpack2(a[p][0]), v1 = unpack2(a[p][1]);
        float2 v2 = unpack2(a[p][2]), v3 = unpack2(a[p][3]);
        int rowA = row0 + r0, rowB = rowA + 1;
        if (rowA < n) ((float4*)g_h)[rowA * 16 + c4] = make_float4(v0.x, v1.x, v2.x, v3.x);
        if (rowB < n) ((float4*)g_h)[rowB * 16 + c4] = make_float4(v0.y, v1.y, v2.y, v3.y);

        u64 ps = 0ull, pd = 0ull;
        fma2(ps, a[p][0], pack2(as4.x, as4.x)); fma2(pd, a[p][0], pack2(ad4.x, ad4.x));
        fma2(ps, a[p][1], pack2(as4.y, as4.y)); fma2(pd, a[p][1], pack2(ad4.y, ad4.y));
        fma2(ps, a[p][2], pack2(as4.z, as4.z)); fma2(pd, a[p][2], pack2(ad4.z, ad4.z));
        fma2(ps, a[p][3], pack2(as4.w, as4.w)); fma2(pd, a[p][3], pack2(ad4.w, ad4.w));
#pragma unroll
        for (int o = 8; o; o >>= 1) {
            u64 tps = __shfl_xor_sync(0xffffffffu, ps, o);
            u64 tpd = __shfl_xor_sync(0xffffffffu, pd, o);
            float2 va = unpack2(ps), vb = unpack2(tps);
            ps = pack2(va.x + vb.x, va.y + vb.y);
            va = unpack2(pd); vb = unpack2(tpd);
            pd = pack2(va.x + vb.x, va.y + vb.y);
        }
        if (c4 == 0) {
            float2 vs = unpack2(ps), vd = unpack2(pd);
            if (rowA < n) { g_as[rowA] = vs.x; g_ad[rowA] = vd.x; }
            if (rowB < n) { g_as[rowB] = vs.y; g_ad[rowB] = vd.y; }
        }
    }
}

// ---------------- GCN pull aggregation (warp/node) ----------------
__global__ void k_gcn_agg(const float* __restrict__ b, int n) {
    int gt = blockIdx.x * blockDim.x + threadIdx.x;
    int d = gt >> 5, lane = gt & 31;
    if (d >= n) return;
    const float2* H2 = (const float2*)g_h;
    float dinv_d = g_dinv[d];
    float2 hv = H2[d * 32 + lane];
    float sn = dinv_d * dinv_d;
    float ax = hv.x * sn, ay = hv.y * sn;
    int beg = g_rs[d], cnt = g_cnt[d];
    for (int c0 = 0; c0 < cnt; c0 += 32) {
        int idx = c0 + lane;
        int s = 0; float nm = 0.f;
        if (idx < cnt) { s = __ldg(&g_csrc[beg + idx]); nm = g_dinv[s] * dinv_d; }
        int m = min(32, cnt - c0);
        int j = 0;
        for (; j + 4 <= m; j += 4) {
            int s0 = __shfl_sync(0xffffffffu, s, j);
            int s1 = __shfl_sync(0xffffffffu, s, j + 1);
            int s2 = __shfl_sync(0xffffffffu, s, j + 2);
            int s3 = __shfl_sync(0xffffffffu, s, j + 3);
            float n0 = __shfl_sync(0xffffffffu, nm, j);
            float n1 = __shfl_sync(0xffffffffu, nm, j + 1);
            float n2 = __shfl_sync(0xffffffffu, nm, j + 2);
            float n3 = __shfl_sync(0xffffffffu, nm, j + 3);
            float2 v0 = H2[s0 * 32 + lane];
            float2 v1 = H2[s1 * 32 + lane];
            float2 v2 = H2[s2 * 32 + lane];
            float2 v3 = H2[s3 * 32 + lane];
            ax = fmaf(n0, v0.x, ax); ay = fmaf(n0, v0.y, ay);
            ax = fmaf(n1, v1.x, ax); ay = fmaf(n1, v1.y, ay);
            ax = fmaf(n2, v2.x, ax); ay = fmaf(n2, v2.y, ay);
            ax = fmaf(n3, v3.x, ax); ay = fmaf(n3, v3.y, ay);
        }
        for (; j < m; j++) {
            int sj = __shfl_sync(0xffffffffu, s, j);
            float nj = __shfl_sync(0xffffffffu, nm, j);
            float2 v = H2[sj * 32 + lane];
            ax = fmaf(nj, v.x, ax); ay = fmaf(nj, v.y, ay);
        }
    }
    float2 bb = ((const float2*)b)[lane];
    float2 o;
    o.x = fmaxf(ax + bb.x, 0.f);
    o.y = fmaxf(ay + bb.y, 0.f);
    ((float2*)g_x)[d * 32 + lane] = o;
}

// ---------------- GAT pull aggregation (warp/node) ----------------
__global__ void k_gat_agg(const float* __restrict__ b, int n) {
    int gt = blockIdx.x * blockDim.x + threadIdx.x;
    int d = gt >> 5, lane = gt & 31;
    if (d >= n) return;
    const float2* H2 = (const float2*)g_h;
    float ad_d = g_ad[d];
    float e0 = g_as[d] + ad_d;
    float l0 = e0 > 0.f ? e0 : 0.2f * e0;
    float wself = __expf(l0);
    float2 hd = H2[d * 32 + lane];
    float ax = wself * hd.x, ay = wself * hd.y;
    float zp = (lane == 0) ? wself : 0.f;
    int beg = g_rs[d], cnt = g_cnt[d];
    for (int c0 = 0; c0 < cnt; c0 += 32) {
        int idx = c0 + lane;
        int s = 0; float w = 0.f;
        if (idx < cnt) {
            s = __ldg(&g_csrc[beg + idx]);
            float ev = g_as[s] + ad_d;
            float lr = ev > 0.f ? ev : 0.2f * ev;
            w = __expf(lr);
        }
        zp += w;
        int m = min(32, cnt - c0);
        int j = 0;
        for (; j + 4 <= m; j += 4) {
            int s0 = __shfl_sync(0xffffffffu, s, j);
            int s1 = __shfl_sync(0xffffffffu, s, j + 1);
            int s2 = __shfl_sync(0xffffffffu, s, j + 2);
            int s3 = __shfl_sync(0xffffffffu, s, j + 3);
            float w0 = __shfl_sync(0xffffffffu, w, j);
            float w1 = __shfl_sync(0xffffffffu, w, j + 1);
            float w2 = __shfl_sync(0xffffffffu, w, j + 2);
            float w3 = __shfl_sync(0xffffffffu, w, j + 3);
            float2 v0 = H2[s0 * 32 + lane];
            float2 v1 = H2[s1 * 32 + lane];
            float2 v2 = H2[s2 * 32 + lane];
            float2 v3 = H2[s3 * 32 + lane];
            ax = fmaf(w0, v0.x, ax); ay = fmaf(w0, v0.y, ay);
            ax = fmaf(w1, v1.x, ax); ay = fmaf(w1, v1.y, ay);
            ax = fmaf(w2, v2.x, ax); ay = fmaf(w2, v2.y, ay);
            ax = fmaf(w3, v3.x, ax); ay = fmaf(w3, v3.y, ay);
        }
        for (; j < m; j++) {
            int sj = __shfl_sync(0xffffffffu, s, j);
            float wj = __shfl_sync(0xffffffffu, w, j);
            float2 v = H2[sj * 32 + lane];
            ax = fmaf(wj, v.x, ax); ay = fmaf(wj, v.y, ay);
        }
    }
#pragma unroll
    for (int o = 16; o; o >>= 1) zp += __shfl_xor_sync(0xffffffffu, zp, o);
    float inv = 1.0f / zp;
    float2 bb = ((const float2*)b)[lane];
    float2 o2;
    o2.x = fmaxf(fmaf(ax, inv, bb.x), 0.f);
    o2.y = fmaxf(fmaf(ay, inv, bb.y), 0.f);
    ((float2*)g_x)[d * 32 + lane] = o2;
}

// ================= fused gate + residual + speed head =================
// 128-row tile; smem aliasing:
//   fusT cols 0..63   = H            (later reused as tb for speed head)
//   fusT cols 64..127 = diffused -> t1(relu res1) -> H_finalT
// dyn smem: fusT[128*130]=16640 | Wb f4[2048]
__global__ void __launch_bounds__(256, 2)
k_final(const float* __restrict__ H,
        const float* __restrict__ gate_W, const float* __restrict__ gate_b,
        const float* __restrict__ res_W1, const float* __restrict__ res_b1,
        const float* __restrict__ res_W2, const float* __restrict__ res_b2,
        const float* __restrict__ sp_W1, const float* __restrict__ sp_b1,
        const float* __restrict__ sp_W2, const float* __restrict__ sp_b2,
        float* __restrict__ delta_out, float* __restrict__ hf_out,
        float* __restrict__ pred_out, int n) {
    extern __shared__ float sm[];
    float* fusT = sm;                        // 16640
    float4* Wb  = (float4*)(sm + 16640);     // 2048 float4

    int tid = threadIdx.x;
    int c4 = tid & 15, rp = tid >> 4;
    int row0 = blockIdx.x * 128;

    // load fusion transposed (128 rows x 128 cols)
    for (int i = tid; i < 4096; i += 256) {
        int rr = i & 127, j = i >> 7;    // j 0..31
        int gr = row0 + rr;
        float4 v = make_float4(0.f, 0.f, 0.f, 0.f);
        if (gr < n) v = (j < 16) ? ((const float4*)H)[gr * 16 + j]
                                 : ((const float4*)g_x)[gr * 16 + (j - 16)];
        fusT[(j * 4 + 0) * STRIDE + rr] = v.x;
        fusT[(j * 4 + 1) * STRIDE + rr] = v.y;
        fusT[(j * 4 + 2) * STRIDE + rr] = v.z;
        fusT[(j * 4 + 3) * STRIDE + rr] = v.w;
    }
    for (int i = tid; i < 2048; i += 256) Wb[i] = ((const float4*)gate_W)[i];
    __syncthreads();

    // ---- gate GEMM (raw acc kept; sigmoid deferred) ----
    u64 ga[4][4];
    {
        float4 b4 = ((const float4*)gate_b)[c4];
        u64 i0 = pack2(b4.x, b4.x), i1 = pack2(b4.y, b4.y);
        u64 i2 = pack2(b4.z, b4.z), i3 = pack2(b4.w, b4.w);
#pragma unroll
        for (int p = 0; p < 4; p++) { ga[p][0] = i0; ga[p][1] = i1; ga[p][2] = i2; ga[p][3] = i3; }
    }
#pragma unroll 4
    for (int k = 0; k < 128; k++) {
        float4 w = Wb[k * 16 + c4];
        u64 w0 = pack2(w.x, w.x), w1 = pack2(w.y, w.y);
        u64 w2 = pack2(w.z, w.z), w3 = pack2(w.w, w.w);
#pragma unroll
        for (int p = 0; p < 4; p++) {
            u64 x = *(const u64*)&fusT[k * STRIDE + 2 * rp + 32 * p];
            fma2(ga[p][0], x, w0); fma2(ga[p][1], x, w1);
            fma2(ga[p][2], x, w2); fma2(ga[p][3], x, w3);
        }
    }
    __syncthreads();
    for (int i = tid; i < 2048; i += 256) Wb[i] = ((const float4*)res_W1)[i];
    __syncthreads();

    // ---- res layer 1 ----
    u64 ra[4][4];
    {
        float4 b4 = ((const float4*)res_b1)[c4];
        u64 i0 = pack2(b4.x, b4.x), i1 = pack2(b4.y, b4.y);
        u64 i2 = pack2(b4.z, b4.z), i3 = pack2(b4.w, b4.w);
#pragma unroll
        for (int p = 0; p < 4; p++) { ra[p][0] = i0; ra[p][1] = i1; ra[p][2] = i2; ra[p][3] = i3; }
    }
#pragma unroll 4
    for (int k = 0; k < 128; k++) {
        float4 w = Wb[k * 16 + c4];
        u64 w0 = pack2(w.x, w.x), w1 = pack2(w.y, w.y);
        u64 w2 = pack2(w.z, w.z), w3 = pack2(w.w, w.w);
#pragma unroll
        for (int p = 0; p < 4; p++) {
            u64 x = *(const u64*)&fusT[k * STRIDE + 2 * rp + 32 * p];
            fma2(ra[p][0], x, w0); fma2(ra[p][1], x, w1);
            fma2(ra[p][2], x, w2); fma2(ra[p][3], x, w3);
        }
    }
    __syncthreads();  // everyone finished reading fusT cols 64..127 (diffused dead)
    // write t1 = relu(res1) into fusT cols 64..127
#pragma unroll
    for (int p = 0; p < 4; p++)
#pragma unroll
        for (int c = 0; c < 4; c++) {
            float2 v = unpack2(ra[p][c]);
            *(u64*)&fusT[(64 + c4 * 4 + c) * STRIDE + 2 * rp + 32 * p] =
                pack2(fmaxf(v.x, 0.f), fmaxf(v.y, 0.f));
        }
    for (int i = tid; i < 1024; i += 256) Wb[i] = ((const float4*)res_W2)[i];
    __syncthreads();

    // ---- res layer 2 ----
    {
        float4 b4 = ((const float4*)res_b2)[c4];
        u64 i0 = pack2(b4.x, b4.x), i1 = pack2(b4.y, b4.y);
        u64 i2 = pack2(b4.z, b4.z), i3 = pack2(b4.w, b4.w);
#pragma unroll
        for (int p = 0; p < 4; p++) { ra[p][0] = i0; ra[p][1] = i1; ra[p][2] = i2; ra[p][3] = i3; }
    }
#pragma unroll 4
    for (int k = 0; k < 64; k++) {
        float4 w = Wb[k * 16 + c4];
        u64 w0 = pack2(w.x, w.x), w1 = pack2(w.y, w.y);
        u64 w2 = pack2(w.z, w.z), w3 = pack2(w.w, w.w);
#pragma unroll
        for (int p = 0; p < 4; p++) {
            u64 x = *(const u64*)&fusT[(64 + k) * STRIDE + 2 * rp + 32 * p];
            fma2(ra[p][0], x, w0); fma2(ra[p][1], x, w1);
            fma2(ra[p][2], x, w2); fma2(ra[p][3], x, w3);
        }
    }
    __syncthreads();  // everyone finished reading t1; cols 64..127 free again

    // ---- delta / H_final: write gmem + store H_finalT into cols 64..127 ----
#pragma unroll
    for (int p = 0; p < 4; p++) {
        int r0 = 2 * rp + 32 * p;
        float d_[4][2], hf_[4][2];
#pragma unroll
        for (int c = 0; c < 4; c++) {
            float2 rv = unpack2(ra[p][c]);
            float2 gvv = unpack2(ga[p][c]);
            float2 hv = unpack2(*(const u64*)&fusT[(c4 * 4 + c) * STRIDE + r0]);
            d_[c][0] = sigmoidf_(gvv.x) * rv.x;
            d_[c][1] = sigmoidf_(gvv.y) * rv.y;
            hf_[c][0] = hv.x + d_[c][0];
            hf_[c][1] = hv.y + d_[c][1];
            *(u64*)&fusT[(64 + c4 * 4 + c) * STRIDE + r0] = pack2(hf_[c][0], hf_[c][1]);
        }
#pragma unroll
        for (int e = 0; e < 2; e++) {
            int row = row0 + r0 + e;
            if (row < n) {
                ((float4*)delta_out)[row * 16 + c4] =
                    make_float4(d_[0][e], d_[1][e], d_[2][e], d_[3][e]);
                ((float4*)hf_out)[row * 16 + c4] =
                    make_float4(hf_[0][e], hf_[1][e], hf_[2][e], hf_[3][e]);
            }
        }
    }
    for (int i = tid; i < 512; i += 256) Wb[i] = ((const float4*)sp_W1)[i];
    __syncthreads();

    // ---- speed head layer 1: cols 2*c4, 2*c4+1 ----
    float* tb = sm;  // reuse H region (cols 0..32): 128 rows x stride 33
    {
        u64 sa[4][2];
        float2 bb = ((const float2*)sp_b1)[c4];
        u64 i0 = pack2(bb.x, bb.x), i1 = pack2(bb.y, bb.y);
#pragma unroll
        for (int p = 0; p < 4; p++) { sa[p][0] = i0; sa[p][1] = i1; }
#pragma unroll 4
        for (int k = 0; k < 64; k++) {
            float2 wv = ((const float2*)Wb)[k * 16 + c4];
            u64 w0 = pack2(wv.x, wv.x), w1 = pack2(wv.y, wv.y);
#pragma unroll
            for (int p = 0; p < 4; p++) {
                u64 x = *(const u64*)&fusT[(64 + k) * STRIDE + 2 * rp + 32 * p];
                fma2(sa[p][0], x, w0); fma2(sa[p][1], x, w1);
            }
        }
        __syncthreads();  // H region reads done (delta step); safe to reuse as tb
#pragma unroll
        for (int p = 0; p < 4; p++) {
            int r0 = 2 * rp + 32 * p;
#pragma unroll
            for (int c = 0; c < 2; c++) {
                float2 v = unpack2(sa[p][c]);
                tb[(r0 + 0) * 33 + c4 * 2 + c] = fmaxf(v.x, 0.f);
                tb[(r0 + 1) * 33 + c4 * 2 + c] = fmaxf(v.y, 0.f);
            }
        }
    }
    __syncthreads();
    if (tid < 128) {
        int gr = row0 + tid;
        if (gr < n) {
            float acc = sp_b2[0];
#pragma unroll
            for (int k = 0; k < 32; k++) acc = fmaf(tb[tid * 33 + k], __ldg(&sp_W2[k]), acc);
            pred_out[gr] = acc;
        }
    }
}

// ---------------- launch ----------------
extern "C" void kernel_launch(void* const* d_in, const int* in_sizes, int n_in,
                              void* d_out, int out_size) {
    const float* H      = (const float*)d_in[0];
    const float* ev     = (const float*)d_in[1];
    const int*   ei     = (const int*)d_in[2];
    const float* enc_W1 = (const float*)d_in[3];
    const float* enc_b1 = (const float*)d_in[4];
    const float* enc_W2 = (const float*)d_in[5];
    const float* enc_b2 = (const float*)d_in[6];
    const float* gcn_W  = (const float*)d_in[7];
    const float* gcn_b  = (const float*)d_in[8];
    const float* gat_W  = (const float*)d_in[9];
    const float* att_s  = (const float*)d_in[10];
    const float* att_d  = (const float*)d_in[11];
    const float* gat_b  = (const float*)d_in[12];
    const float* gate_W = (const float*)d_in[13];
    const float* gate_b = (const float*)d_in[14];
    const float* res_W1 = (const float*)d_in[15];
    const float* res_b1 = (const float*)d_in[16];
    const float* res_W2 = (const float*)d_in[17];
    const float* res_b2 = (const float*)d_in[18];
    const float* sp_W1  = (const float*)d_in[19];
    const float* sp_b1  = (const float*)d_in[20];
    const float* sp_W2  = (const float*)d_in[21];
    const float* sp_b2  = (const float*)d_in[22];

    int n = in_sizes[0] / 64;
    int E = in_sizes[2] / 2;

    float* delta = (float*)d_out;
    float* hf    = delta + (size_t)n * 64;
    float* pred  = hf + (size_t)n * 64;

    int nb128  = (n + 127) / 128;
    int nbN    = (n + 255) / 256;
    int nbE    = (E + 255) / 256;
    int nb1024 = (n + 1023) / 1024;
    int nbW    = (n * 32 + 255) / 256;

    const int ENC_SMEM = (1040 + 8320) * 4 + 1024 * 16;  // 53824
    const int GAT_SMEM = 8320 * 4 + 1024 * 16;           // 49664
    const int FIN_SMEM = 16640 * 4 + 2048 * 16;          // 99328
    cudaFuncSetAttribute(k_encgemm, cudaFuncAttributeMaxDynamicSharedMemorySize, ENC_SMEM);
    cudaFuncSetAttribute(k_gemm_gat, cudaFuncAttributeMaxDynamicSharedMemorySize, GAT_SMEM);
    cudaFuncSetAttribute(k_final, cudaFuncAttributeMaxDynamicSharedMemorySize, FIN_SMEM);

    k_zero<<<nbN, 256>>>(n);
    k_cnt<<<nbE, 256>>>(ei, E);
    k_scanA<<<nb1024, 1024>>>(n);
    k_encgemm<<<nb128, 256, ENC_SMEM>>>(ev, enc_W1, enc_b1, enc_W2, enc_b2, gcn_W, n);
    k_scanB<<<1, 128>>>(nb1024);
    k_scanC<<<nbN, 256>>>(n);
    k_csr<<<nbE, 256>>>(ei, E);
    k_gcn_agg<<<nbW, 256>>>(gcn_b, n);
    k_gemm_gat<<<nb128, 256, GAT_SMEM>>>(gat_W, att_s, att_d, n);
    k_gat_agg<<<nbW, 256>>>(gat_b, n);
    k_final<<<nb128, 256, FIN_SMEM>>>(H, gate_W, gate_b, res_W1, res_b1, res_W2, res_b2,
                                      sp_W1, sp_b1, sp_W2, sp_b2, delta, hf, pred, n);
}

// round 8
// speedup vs baseline: 1.6141x; 1.0325x over previous
#include <cuda_runtime.h>

#define D 64
#define NMAX 100000
#define EMAX 1600000

typedef unsigned long long u64;

// ---------------- scratch (static device globals) ----------------
__device__ float g_h[NMAX * D];    // h (GCN) then h2 (GAT)
__device__ float g_x[NMAX * D];    // GCN output x, then diffused
__device__ float g_as[NMAX];
__device__ float g_ad[NMAX];
__device__ float g_dinv[NMAX];
__device__ int   g_cnt[NMAX];
__device__ int   g_rs[NMAX];
__device__ int   g_cur[NMAX];
__device__ int   g_bsum[256];
__device__ int   g_csrc[EMAX];

// ---------------- helpers ----------------
__device__ __forceinline__ void fma2(u64& acc, u64 a, u64 b) {
    asm("fma.rn.f32x2 %0, %1, %2, %0;" : "+l"(acc) : "l"(a), "l"(b));
}
__device__ __forceinline__ u64 pack2(float lo, float hi) {
    u64 d; asm("mov.b64 %0, {%1, %2};" : "=l"(d) : "f"(lo), "f"(hi)); return d;
}
__device__ __forceinline__ float2 unpack2(u64 v) {
    float2 r; asm("mov.b64 {%0, %1}, %2;" : "=f"(r.x), "=f"(r.y) : "l"(v)); return r;
}
__device__ __forceinline__ float sigmoidf_(float x) { return 1.0f / (1.0f + __expf(-x)); }

#define STRIDE 130  // 128-row tile + 2 pad

// ---------------- CSR build ----------------
__global__ void k_zero(int n) {
    int i = blockIdx.x * blockDim.x + threadIdx.x;
    if (i < n) g_cnt[i] = 0;
}
__global__ void k_cnt(const int* __restrict__ ei, int E) {
    int e = blockIdx.x * blockDim.x + threadIdx.x;
    if (e < E) atomicAdd(&g_cnt[ei[E + e]], 1);
}
__global__ void k_scanA(int n) {
    __shared__ int s[1024];
    int tid = threadIdx.x;
    int i = blockIdx.x * 1024 + tid;
    int v = (i < n) ? g_cnt[i] : 0;
    s[tid] = v; __syncthreads();
    for (int off = 1; off < 1024; off <<= 1) {
        int t = (tid >= off) ? s[tid - off] : 0;
        __syncthreads();
        s[tid] += t; __syncthreads();
    }
    if (i < n) g_rs[i] = s[tid] - v;
    if (tid == 1023) g_bsum[blockIdx.x] = s[1023];
}
__global__ void k_scanB(int nb) {
    __shared__ int s[128];
    int tid = threadIdx.x;
    int v = (tid < nb) ? g_bsum[tid] : 0;
    s[tid] = v; __syncthreads();
    for (int off = 1; off < 128; off <<= 1) {
        int t = (tid >= off) ? s[tid - off] : 0;
        __syncthreads();
        s[tid] += t; __syncthreads();
    }
    if (tid < nb) g_bsum[tid] = s[tid] - v;
}
__global__ void k_scanC(int n) {
    int i = blockIdx.x * blockDim.x + threadIdx.x;
    if (i >= n) return;
    int base = g_bsum[i >> 10];
    int r = g_rs[i] + base;
    g_rs[i] = r;
    g_cur[i] = r;
    g_dinv[i] = rsqrtf((float)g_cnt[i] + 1.0f);  // deg includes self-loop
}
__global__ void k_csr(const int* __restrict__ ei, int E) {
    int e = blockIdx.x * blockDim.x + threadIdx.x;
    if (e >= E) return;
    int s = ei[e], d = ei[E + e];
    int p = atomicAdd(&g_cur[d], 1);
    g_csrc[p] = s;
}

// ================= fused encoder MLP + GCN weight GEMM =================
__global__ void k_encgemm(const float* __restrict__ ev,
                          const float* __restrict__ W1, const float* __restrict__ b1,
                          const float* __restrict__ W2, const float* __restrict__ b2,
                          const float* __restrict__ gcnW, int n) {
    extern __shared__ float sm[];
    float* evT = sm;                     // 1040
    float* t1T = sm + 1040;              // 8320
    float4* Wb = (float4*)(sm + 9360);   // 1024 float4

    int tid = threadIdx.x;
    int c4 = tid & 15, rp = tid >> 4;
    int row0 = blockIdx.x * 128;

    {
        int rr = tid & 127, q = tid >> 7;
        int gr = row0 + rr;
        float4 v = make_float4(0.f, 0.f, 0.f, 0.f);
        if (gr < n) v = ((const float4*)ev)[gr * 2 + q];
        evT[(q * 4 + 0) * STRIDE + rr] = v.x;
        evT[(q * 4 + 1) * STRIDE + rr] = v.y;
        evT[(q * 4 + 2) * STRIDE + rr] = v.z;
        evT[(q * 4 + 3) * STRIDE + rr] = v.w;
    }
    if (tid < 128) Wb[tid] = ((const float4*)W1)[tid];
    __syncthreads();

    u64 a[4][4];
    {
        float4 b4 = ((const float4*)b1)[c4];
        u64 i0 = pack2(b4.x, b4.x), i1 = pack2(b4.y, b4.y);
        u64 i2 = pack2(b4.z, b4.z), i3 = pack2(b4.w, b4.w);
#pragma unroll
        for (int p = 0; p < 4; p++) { a[p][0] = i0; a[p][1] = i1; a[p][2] = i2; a[p][3] = i3; }
    }
#pragma unroll
    for (int k = 0; k < 8; k++) {
        float4 w = Wb[k * 16 + c4];
        u64 w0 = pack2(w.x, w.x), w1 = pack2(w.y, w.y);
        u64 w2 = pack2(w.z, w.z), w3 = pack2(w.w, w.w);
#pragma unroll
        for (int p = 0; p < 4; p++) {
            u64 x = *(const u64*)&evT[k * STRIDE + 2 * rp + 32 * p];
            fma2(a[p][0], x, w0); fma2(a[p][1], x, w1);
            fma2(a[p][2], x, w2); fma2(a[p][3], x, w3);
        }
    }
#pragma unroll
    for (int p = 0; p < 4; p++)
#pragma unroll
        for (int c = 0; c < 4; c++) {
            float2 v = unpack2(a[p][c]);
            *(u64*)&t1T[(c4 * 4 + c) * STRIDE + 2 * rp + 32 * p] =
                pack2(fmaxf(v.x, 0.f), fmaxf(v.y, 0.f));
        }
    __syncthreads();
    for (int i = tid; i < 1024; i += 256) Wb[i] = ((const float4*)W2)[i];
    __syncthreads();

    {
        float4 b4 = ((const float4*)b2)[c4];
        u64 i0 = pack2(b4.x, b4.x), i1 = pack2(b4.y, b4.y);
        u64 i2 = pack2(b4.z, b4.z), i3 = pack2(b4.w, b4.w);
#pragma unroll
        for (int p = 0; p < 4; p++) { a[p][0] = i0; a[p][1] = i1; a[p][2] = i2; a[p][3] = i3; }
    }
#pragma unroll 4
    for (int k = 0; k < 64; k++) {
        float4 w = Wb[k * 16 + c4];
        u64 w0 = pack2(w.x, w.x), w1 = pack2(w.y, w.y);
        u64 w2 = pack2(w.z, w.z), w3 = pack2(w.w, w.w);
#pragma unroll
        for (int p = 0; p < 4; p++) {
            u64 x = *(const u64*)&t1T[k * STRIDE + 2 * rp + 32 * p];
            fma2(a[p][0], x, w0); fma2(a[p][1], x, w1);
            fma2(a[p][2], x, w2); fma2(a[p][3], x, w3);
        }
    }
    __syncthreads();
#pragma unroll
    for (int p = 0; p < 4; p++)
#pragma unroll
        for (int c = 0; c < 4; c++)
            *(u64*)&t1T[(c4 * 4 + c) * STRIDE + 2 * rp + 32 * p] = a[p][c];
    for (int i = tid; i < 1024; i += 256) Wb[i] = ((const float4*)gcnW)[i];
    __syncthreads();

#pragma unroll
    for (int p = 0; p < 4; p++)
#pragma unroll
        for (int c = 0; c < 4; c++) a[p][c] = 0ull;
#pragma unroll 4
    for (int k = 0; k < 64; k++) {
        float4 w = Wb[k * 16 + c4];
        u64 w0 = pack2(w.x, w.x), w1 = pack2(w.y, w.y);
        u64 w2 = pack2(w.z, w.z), w3 = pack2(w.w, w.w);
#pragma unroll
        for (int p = 0; p < 4; p++) {
            u64 x = *(const u64*)&t1T[k * STRIDE + 2 * rp + 32 * p];
            fma2(a[p][0], x, w0); fma2(a[p][1], x, w1);
            fma2(a[p][2], x, w2); fma2(a[p][3], x, w3);
        }
    }
#pragma unroll
    for (int p = 0; p < 4; p++) {
        int r0 = 2 * rp + 32 * p;
        float2 v0 = unpack2(a[p][0]), v1 = unpack2(a[p][1]);
        float2 v2 = unpack2(a[p][2]), v3 = unpack2(a[p][3]);
        int rowA = row0 + r0, rowB = rowA + 1;
        if (rowA < n) ((float4*)g_h)[rowA * 16 + c4] = make_float4(v0.x, v1.x, v2.x, v3.x);
        if (rowB < n) ((float4*)g_h)[rowB * 16 + c4] = make_float4(v0.y, v1.y, v2.y, v3.y);
    }
}

// ================= GAT weight GEMM + fused att coefficients =================
__global__ void k_gemm_gat(const float* __restrict__ W,
                           const float* __restrict__ att_s, const float* __restrict__ att_d,
                           int n) {
    extern __shared__ float sm[];
    float* xT = sm;                     // 8320
    float4* Ws = (float4*)(sm + 8320);  // 1024 float4

    int tid = threadIdx.x;
    int c4 = tid & 15, rp = tid >> 4;
    int row0 = blockIdx.x * 128;

    for (int i = tid; i < 2048; i += 256) {
        int rr = i & 127, j = i >> 7;
        int gr = row0 + rr;
        float4 v = make_float4(0.f, 0.f, 0.f, 0.f);
        if (gr < n) v = ((const float4*)g_x)[gr * 16 + j];
        xT[(j * 4 + 0) * STRIDE + rr] = v.x;
        xT[(j * 4 + 1) * STRIDE + rr] = v.y;
        xT[(j * 4 + 2) * STRIDE + rr] = v.z;
        xT[(j * 4 + 3) * STRIDE + rr] = v.w;
    }
    for (int i = tid; i < 1024; i += 256) Ws[i] = ((const float4*)W)[i];
    __syncthreads();

    u64 a[4][4];
#pragma unroll
    for (int p = 0; p < 4; p++)
#pragma unroll
        for (int c = 0; c < 4; c++) a[p][c] = 0ull;
#pragma unroll 4
    for (int k = 0; k < 64; k++) {
        float4 w = Ws[k * 16 + c4];
        u64 w0 = pack2(w.x, w.x), w1 = pack2(w.y, w.y);
        u64 w2 = pack2(w.z, w.z), w3 = pack2(w.w, w.w);
#pragma unroll
        for (int p = 0; p < 4; p++) {
            u64 x = *(const u64*)&xT[k * STRIDE + 2 * rp + 32 * p];
            fma2(a[p][0], x, w0); fma2(a[p][1], x, w1);
            fma2(a[p][2], x, w2); fma2(a[p][3], x, w3);
        }
    }

    float4 as4 = ((const float4*)att_s)[c4];
    float4 ad4 = ((const float4*)att_d)[c4];
#pragma unroll
    for (int p = 0; p < 4; p++) {
        int r0 = 2 * rp + 32 * p;
        float2 v0 = unpack2(a[p][0]), v1 = unpack2(a[p][1]);
        float2 v2 = unpack2(a[p][2]), v3 = unpack2(a[p][3]);
        int rowA = row0 + r0, rowB = rowA + 1;
        if (rowA < n) ((float4*)g_h)[rowA * 16 + c4] = make_float4(v0.x, v1.x, v2.x, v3.x);
        if (rowB < n) ((float4*)g_h)[rowB * 16 + c4] = make_float4(v0.y, v1.y, v2.y, v3.y);

        u64 ps = 0ull, pd = 0ull;
        fma2(ps, a[p][0], pack2(as4.x, as4.x)); fma2(pd, a[p][0], pack2(ad4.x, ad4.x));
        fma2(ps, a[p][1], pack2(as4.y, as4.y)); fma2(pd, a[p][1], pack2(ad4.y, ad4.y));
        fma2(ps, a[p][2], pack2(as4.z, as4.z)); fma2(pd, a[p][2], pack2(ad4.z, ad4.z));
        fma2(ps, a[p][3], pack2(as4.w, as4.w)); fma2(pd, a[p][3], pack2(ad4.w, ad4.w));
#pragma unroll
        for (int o = 8; o; o >>= 1) {
            u64 tps = __shfl_xor_sync(0xffffffffu, ps, o);
            u64 tpd = __shfl_xor_sync(0xffffffffu, pd, o);
            float2 va = unpack2(ps), vb = unpack2(tps);
            ps = pack2(va.x + vb.x, va.y + vb.y);
            va = unpack2(pd); vb = unpack2(tpd);
            pd = pack2(va.x + vb.x, va.y + vb.y);
        }
        if (c4 == 0) {
            float2 vs = unpack2(ps), vd = unpack2(pd);
            if (rowA < n) { g_as[rowA] = vs.x; g_ad[rowA] = vd.x; }
            if (rowB < n) { g_as[rowB] = vs.y; g_ad[rowB] = vd.y; }
        }
    }
}

// ---------------- GCN pull aggregation (warp/node) ----------------
__global__ void k_gcn_agg(const float* __restrict__ b, int n) {
    int gt = blockIdx.x * blockDim.x + threadIdx.x;
    int d = gt >> 5, lane = gt & 31;
    if (d >= n) return;
    const float2* H2 = (const float2*)g_h;
    float dinv_d = g_dinv[d];
    float2 hv = H2[d * 32 + lane];
    float sn = dinv_d * dinv_d;
    float ax = hv.x * sn, ay = hv.y * sn;
    int beg = g_rs[d], cnt = g_cnt[d];
    for (int c0 = 0; c0 < cnt; c0 += 32) {
        int idx = c0 + lane;
        int s = 0; float nm = 0.f;
        if (idx < cnt) { s = __ldg(&g_csrc[beg + idx]); nm = g_dinv[s] * dinv_d; }
        int m = min(32, cnt - c0);
        int j = 0;
        for (; j + 4 <= m; j += 4) {
            int s0 = __shfl_sync(0xffffffffu, s, j);
            int s1 = __shfl_sync(0xffffffffu, s, j + 1);
            int s2 = __shfl_sync(0xffffffffu, s, j + 2);
            int s3 = __shfl_sync(0xffffffffu, s, j + 3);
            float n0 = __shfl_sync(0xffffffffu, nm, j);
            float n1 = __shfl_sync(0xffffffffu, nm, j + 1);
            float n2 = __shfl_sync(0xffffffffu, nm, j + 2);
            float n3 = __shfl_sync(0xffffffffu, nm, j + 3);
            float2 v0 = H2[s0 * 32 + lane];
            float2 v1 = H2[s1 * 32 + lane];
            float2 v2 = H2[s2 * 32 + lane];
            float2 v3 = H2[s3 * 32 + lane];
            ax = fmaf(n0, v0.x, ax); ay = fmaf(n0, v0.y, ay);
            ax = fmaf(n1, v1.x, ax); ay = fmaf(n1, v1.y, ay);
            ax = fmaf(n2, v2.x, ax); ay = fmaf(n2, v2.y, ay);
            ax = fmaf(n3, v3.x, ax); ay = fmaf(n3, v3.y, ay);
        }
        for (; j < m; j++) {
            int sj = __shfl_sync(0xffffffffu, s, j);
            float nj = __shfl_sync(0xffffffffu, nm, j);
            float2 v = H2[sj * 32 + lane];
            ax = fmaf(nj, v.x, ax); ay = fmaf(nj, v.y, ay);
        }
    }
    float2 bb = ((const float2*)b)[lane];
    float2 o;
    o.x = fmaxf(ax + bb.x, 0.f);
    o.y = fmaxf(ay + bb.y, 0.f);
    ((float2*)g_x)[d * 32 + lane] = o;
}

// ---------------- GAT pull aggregation (warp/node) ----------------
__global__ void k_gat_agg(const float* __restrict__ b, int n) {
    int gt = blockIdx.x * blockDim.x + threadIdx.x;
    int d = gt >> 5, lane = gt & 31;
    if (d >= n) return;
    const float2* H2 = (const float2*)g_h;
    float ad_d = g_ad[d];
    float e0 = g_as[d] + ad_d;
    float l0 = e0 > 0.f ? e0 : 0.2f * e0;
    float wself = __expf(l0);
    float2 hd = H2[d * 32 + lane];
    float ax = wself * hd.x, ay = wself * hd.y;
    float zp = (lane == 0) ? wself : 0.f;
    int beg = g_rs[d], cnt = g_cnt[d];
    for (int c0 = 0; c0 < cnt; c0 += 32) {
        int idx = c0 + lane;
        int s = 0; float w = 0.f;
        if (idx < cnt) {
            s = __ldg(&g_csrc[beg + idx]);
            float ev = g_as[s] + ad_d;
            float lr = ev > 0.f ? ev : 0.2f * ev;
            w = __expf(lr);
        }
        zp += w;
        int m = min(32, cnt - c0);
        int j = 0;
        for (; j + 4 <= m; j += 4) {
            int s0 = __shfl_sync(0xffffffffu, s, j);
            int s1 = __shfl_sync(0xffffffffu, s, j + 1);
            int s2 = __shfl_sync(0xffffffffu, s, j + 2);
            int s3 = __shfl_sync(0xffffffffu, s, j + 3);
            float w0 = __shfl_sync(0xffffffffu, w, j);
            float w1 = __shfl_sync(0xffffffffu, w, j + 1);
            float w2 = __shfl_sync(0xffffffffu, w, j + 2);
            float w3 = __shfl_sync(0xffffffffu, w, j + 3);
            float2 v0 = H2[s0 * 32 + lane];
            float2 v1 = H2[s1 * 32 + lane];
            float2 v2 = H2[s2 * 32 + lane];
            float2 v3 = H2[s3 * 32 + lane];
            ax = fmaf(w0, v0.x, ax); ay = fmaf(w0, v0.y, ay);
            ax = fmaf(w1, v1.x, ax); ay = fmaf(w1, v1.y, ay);
            ax = fmaf(w2, v2.x, ax); ay = fmaf(w2, v2.y, ay);
            ax = fmaf(w3, v3.x, ax); ay = fmaf(w3, v3.y, ay);
        }
        for (; j < m; j++) {
            int sj = __shfl_sync(0xffffffffu, s, j);
            float wj = __shfl_sync(0xffffffffu, w, j);
            float2 v = H2[sj * 32 + lane];
            ax = fmaf(wj, v.x, ax); ay = fmaf(wj, v.y, ay);
        }
    }
#pragma unroll
    for (int o = 16; o; o >>= 1) zp += __shfl_xor_sync(0xffffffffu, zp, o);
    float inv = 1.0f / zp;
    float2 bb = ((const float2*)b)[lane];
    float2 o2;
    o2.x = fmaxf(fmaf(ax, inv, bb.x), 0.f);
    o2.y = fmaxf(fmaf(ay, inv, bb.y), 0.f);
    ((float2*)g_x)[d * 32 + lane] = o2;
}

// ================= fused gate + residual + speed head =================
__global__ void __launch_bounds__(256, 2)
k_final(const float* __restrict__ H,
        const float* __restrict__ gate_W, const float* __restrict__ gate_b,
        const float* __restrict__ res_W1, const float* __restrict__ res_b1,
        const float* __restrict__ res_W2, const float* __restrict__ res_b2,
        const float* __restrict__ sp_W1, const float* __restrict__ sp_b1,
        const float* __restrict__ sp_W2, const float* __restrict__ sp_b2,
        float* __restrict__ delta_out, float* __restrict__ hf_out,
        float* __restrict__ pred_out, int n) {
    extern __shared__ float sm[];
    float* fusT = sm;                        // 16640
    float4* Wb  = (float4*)(sm + 16640);     // 2048 float4

    int tid = threadIdx.x;
    int c4 = tid & 15, rp = tid >> 4;
    int row0 = blockIdx.x * 128;

    for (int i = tid; i < 4096; i += 256) {
        int rr = i & 127, j = i >> 7;
        int gr = row0 + rr;
        float4 v = make_float4(0.f, 0.f, 0.f, 0.f);
        if (gr < n) v = (j < 16) ? ((const float4*)H)[gr * 16 + j]
                                 : ((const float4*)g_x)[gr * 16 + (j - 16)];
        fusT[(j * 4 + 0) * STRIDE + rr] = v.x;
        fusT[(j * 4 + 1) * STRIDE + rr] = v.y;
        fusT[(j * 4 + 2) * STRIDE + rr] = v.z;
        fusT[(j * 4 + 3) * STRIDE + rr] = v.w;
    }
    for (int i = tid; i < 2048; i += 256) Wb[i] = ((const float4*)gate_W)[i];
    __syncthreads();

    u64 ga[4][4];
    {
        float4 b4 = ((const float4*)gate_b)[c4];
        u64 i0 = pack2(b4.x, b4.x), i1 = pack2(b4.y, b4.y);
        u64 i2 = pack2(b4.z, b4.z), i3 = pack2(b4.w, b4.w);
#pragma unroll
        for (int p = 0; p < 4; p++) { ga[p][0] = i0; ga[p][1] = i1; ga[p][2] = i2; ga[p][3] = i3; }
    }
#pragma unroll 4
    for (int k = 0; k < 128; k++) {
        float4 w = Wb[k * 16 + c4];
        u64 w0 = pack2(w.x, w.x), w1 = pack2(w.y, w.y);
        u64 w2 = pack2(w.z, w.z), w3 = pack2(w.w, w.w);
#pragma unroll
        for (int p = 0; p < 4; p++) {
            u64 x = *(const u64*)&fusT[k * STRIDE + 2 * rp + 32 * p];
            fma2(ga[p][0], x, w0); fma2(ga[p][1], x, w1);
            fma2(ga[p][2], x, w2); fma2(ga[p][3], x, w3);
        }
    }
    __syncthreads();
    for (int i = tid; i < 2048; i += 256) Wb[i] = ((const float4*)res_W1)[i];
    __syncthreads();

    u64 ra[4][4];
    {
        float4 b4 = ((const float4*)res_b1)[c4];
        u64 i0 = pack2(b4.x, b4.x), i1 = pack2(b4.y, b4.y);
        u64 i2 = pack2(b4.z, b4.z), i3 = pack2(b4.w, b4.w);
#pragma unroll
        for (int p = 0; p < 4; p++) { ra[p][0] = i0; ra[p][1] = i1; ra[p][2] = i2; ra[p][3] = i3; }
    }
#pragma unroll 4
    for (int k = 0; k < 128; k++) {
        float4 w = Wb[k * 16 + c4];
        u64 w0 = pack2(w.x, w.x), w1 = pack2(w.y, w.y);
        u64 w2 = pack2(w.z, w.z), w3 = pack2(w.w, w.w);
#pragma unroll
        for (int p = 0; p < 4; p++) {
            u64 x = *(const u64*)&fusT[k * STRIDE + 2 * rp + 32 * p];
            fma2(ra[p][0], x, w0); fma2(ra[p][1], x, w1);
            fma2(ra[p][2], x, w2); fma2(ra[p][3], x, w3);
        }
    }
    __syncthreads();
#pragma unroll
    for (int p = 0; p < 4; p++)
#pragma unroll
        for (int c = 0; c < 4; c++) {
            float2 v = unpack2(ra[p][c]);
            *(u64*)&fusT[(64 + c4 * 4 + c) * STRIDE + 2 * rp + 32 * p] =
                pack2(fmaxf(v.x, 0.f), fmaxf(v.y, 0.f));
        }
    for (int i = tid; i < 1024; i += 256) Wb[i] = ((const float4*)res_W2)[i];
    __syncthreads();

    {
        float4 b4 = ((const float4*)res_b2)[c4];
        u64 i0 = pack2(b4.x, b4.x), i1 = pack2(b4.y, b4.y);
        u64 i2 = pack2(b4.z, b4.z), i3 = pack2(b4.w, b4.w);
#pragma unroll
        for (int p = 0; p < 4; p++) { ra[p][0] = i0; ra[p][1] = i1; ra[p][2] = i2; ra[p][3] = i3; }
    }
#pragma unroll 4
    for (int k = 0; k < 64; k++) {
        float4 w = Wb[k * 16 + c4];
        u64 w0 = pack2(w.x, w.x), w1 = pack2(w.y, w.y);
        u64 w2 = pack2(w.z, w.z), w3 = pack2(w.w, w.w);
#pragma unroll
        for (int p = 0; p < 4; p++) {
            u64 x = *(const u64*)&fusT[(64 + k) * STRIDE + 2 * rp + 32 * p];
            fma2(ra[p][0], x, w0); fma2(ra[p][1], x, w1);
            fma2(ra[p][2], x, w2); fma2(ra[p][3], x, w3);
        }
    }
    __syncthreads();

#pragma unroll
    for (int p = 0; p < 4; p++) {
        int r0 = 2 * rp + 32 * p;
        float d_[4][2], hf_[4][2];
#pragma unroll
        for (int c = 0; c < 4; c++) {
            float2 rv = unpack2(ra[p][c]);
            float2 gvv = unpack2(ga[p][c]);
            float2 hv = unpack2(*(const u64*)&fusT[(c4 * 4 + c) * STRIDE + r0]);
            d_[c][0] = sigmoidf_(gvv.x) * rv.x;
            d_[c][1] = sigmoidf_(gvv.y) * rv.y;
            hf_[c][0] = hv.x + d_[c][0];
            hf_[c][1] = hv.y + d_[c][1];
            *(u64*)&fusT[(64 + c4 * 4 + c) * STRIDE + r0] = pack2(hf_[c][0], hf_[c][1]);
        }
#pragma unroll
        for (int e = 0; e < 2; e++) {
            int row = row0 + r0 + e;
            if (row < n) {
                ((float4*)delta_out)[row * 16 + c4] =
                    make_float4(d_[0][e], d_[1][e], d_[2][e], d_[3][e]);
                ((float4*)hf_out)[row * 16 + c4] =
                    make_float4(hf_[0][e], hf_[1][e], hf_[2][e], hf_[3][e]);
            }
        }
    }
    for (int i = tid; i < 512; i += 256) Wb[i] = ((const float4*)sp_W1)[i];
    __syncthreads();

    float* tb = sm;  // reuse H region
    {
        u64 sa[4][2];
        float2 bb = ((const float2*)sp_b1)[c4];
        u64 i0 = pack2(bb.x, bb.x), i1 = pack2(bb.y, bb.y);
#pragma unroll
        for (int p = 0; p < 4; p++) { sa[p][0] = i0; sa[p][1] = i1; }
#pragma unroll 4
        for (int k = 0; k < 64; k++) {
            float2 wv = ((const float2*)Wb)[k * 16 + c4];
            u64 w0 = pack2(wv.x, wv.x), w1 = pack2(wv.y, wv.y);
#pragma unroll
            for (int p = 0; p < 4; p++) {
                u64 x = *(const u64*)&fusT[(64 + k) * STRIDE + 2 * rp + 32 * p];
                fma2(sa[p][0], x, w0); fma2(sa[p][1], x, w1);
            }
        }
        __syncthreads();
#pragma unroll
        for (int p = 0; p < 4; p++) {
            int r0 = 2 * rp + 32 * p;
#pragma unroll
            for (int c = 0; c < 2; c++) {
                float2 v = unpack2(sa[p][c]);
                tb[(r0 + 0) * 33 + c4 * 2 + c] = fmaxf(v.x, 0.f);
                tb[(r0 + 1) * 33 + c4 * 2 + c] = fmaxf(v.y, 0.f);
            }
        }
    }
    __syncthreads();
    if (tid < 128) {
        int gr = row0 + tid;
        if (gr < n) {
            float acc = sp_b2[0];
#pragma unroll
            for (int k = 0; k < 32; k++) acc = fmaf(tb[tid * 33 + k], __ldg(&sp_W2[k]), acc);
            pred_out[gr] = acc;
        }
    }
}

// ---------------- launch ----------------
extern "C" void kernel_launch(void* const* d_in, const int* in_sizes, int n_in,
                              void* d_out, int out_size) {
    const float* H      = (const float*)d_in[0];
    const float* ev     = (const float*)d_in[1];
    const int*   ei     = (const int*)d_in[2];
    const float* enc_W1 = (const float*)d_in[3];
    const float* enc_b1 = (const float*)d_in[4];
    const float* enc_W2 = (const float*)d_in[5];
    const float* enc_b2 = (const float*)d_in[6];
    const float* gcn_W  = (const float*)d_in[7];
    const float* gcn_b  = (const float*)d_in[8];
    const float* gat_W  = (const float*)d_in[9];
    const float* att_s  = (const float*)d_in[10];
    const float* att_d  = (const float*)d_in[11];
    const float* gat_b  = (const float*)d_in[12];
    const float* gate_W = (const float*)d_in[13];
    const float* gate_b = (const float*)d_in[14];
    const float* res_W1 = (const float*)d_in[15];
    const float* res_b1 = (const float*)d_in[16];
    const float* res_W2 = (const float*)d_in[17];
    const float* res_b2 = (const float*)d_in[18];
    const float* sp_W1  = (const float*)d_in[19];
    const float* sp_b1  = (const float*)d_in[20];
    const float* sp_W2  = (const float*)d_in[21];
    const float* sp_b2  = (const float*)d_in[22];

    int n = in_sizes[0] / 64;
    int E = in_sizes[2] / 2;

    float* delta = (float*)d_out;
    float* hf    = delta + (size_t)n * 64;
    float* pred  = hf + (size_t)n * 64;

    int nb128  = (n + 127) / 128;
    int nbN    = (n + 255) / 256;
    int nbE    = (E + 255) / 256;
    int nb1024 = (n + 1023) / 1024;
    int nbW    = (n * 32 + 255) / 256;

    const int ENC_SMEM = (1040 + 8320) * 4 + 1024 * 16;  // 53824
    const int GAT_SMEM = 8320 * 4 + 1024 * 16;           // 49664
    const int FIN_SMEM = 16640 * 4 + 2048 * 16;          // 99328

    // one-time setup (runs during the non-captured correctness call)
    static cudaStream_t s2 = nullptr;
    static cudaEvent_t evFork = nullptr, evJoin = nullptr;
    if (!s2) {
        cudaStreamCreate(&s2);
        cudaEventCreateWithFlags(&evFork, cudaEventDisableTiming);
        cudaEventCreateWithFlags(&evJoin, cudaEventDisableTiming);
        cudaFuncSetAttribute(k_encgemm, cudaFuncAttributeMaxDynamicSharedMemorySize, ENC_SMEM);
        cudaFuncSetAttribute(k_gemm_gat, cudaFuncAttributeMaxDynamicSharedMemorySize, GAT_SMEM);
        cudaFuncSetAttribute(k_final, cudaFuncAttributeMaxDynamicSharedMemorySize, FIN_SMEM);
    }

    // fork: encoder GEMM chain on s2, CSR build on main (default) stream
    cudaEventRecord(evFork, 0);
    cudaStreamWaitEvent(s2, evFork, 0);
    k_encgemm<<<nb128, 256, ENC_SMEM, s2>>>(ev, enc_W1, enc_b1, enc_W2, enc_b2, gcn_W, n);
    cudaEventRecord(evJoin, s2);

    k_zero<<<nbN, 256>>>(n);
    k_cnt<<<nbE, 256>>>(ei, E);
    k_scanA<<<nb1024, 1024>>>(n);
    k_scanB<<<1, 128>>>(nb1024);
    k_scanC<<<nbN, 256>>>(n);
    k_csr<<<nbE, 256>>>(ei, E);

    // join: aggregation needs both h (s2) and CSR (main)
    cudaStreamWaitEvent(0, evJoin, 0);
    k_gcn_agg<<<nbW, 256>>>(gcn_b, n);
    k_gemm_gat<<<nb128, 256, GAT_SMEM>>>(gat_W, att_s, att_d, n);
    k_gat_agg<<<nbW, 256>>>(gat_b, n);
    k_final<<<nb128, 256, FIN_SMEM>>>(H, gate_W, gate_b, res_W1, res_b1, res_W2, res_b2,
                                      sp_W1, sp_b1, sp_W2, sp_b2, delta, hf, pred, n);
}